// round 2
// baseline (speedup 1.0000x reference)
#include <cuda_runtime.h>
#include <math.h>

#define SEQ    2048
#define DM     768
#define NH     4
#define HD     192
#define BATCH  4
#define BHT    16           // BATCH*NH
#define NEGV   (-1000000000.0f)

// ---- device scratch (allocation-free rule: static __device__ arrays) ----
__device__ float g_Q [BHT*SEQ*HD];
__device__ float g_K [BHT*SEQ*HD];
__device__ float g_V [BHT*SEQ*HD];
__device__ float g_X1[BHT*SEQ*HD];
__device__ float g_Sc[BHT*SEQ*SEQ];      // 268 MB raw masked scores
__device__ float g_cm[BHT*SEQ];          // per-column max
__device__ float g_ci[BHT*SEQ];          // per-column 1/sum

// ============================================================
// K1: QKV projection.  C = X @ W^T + b   (NT GEMM, 64x64x16 tiles)
// X: [8192, 768] row-major; W: [768, 768] row-major (output-major, K-contig)
// Out layout: (b, h, s, d)
// ============================================================
__global__ __launch_bounds__(256) void k_qkv(
    const float* __restrict__ X,
    const float* __restrict__ Wq, const float* __restrict__ bq,
    const float* __restrict__ Wk, const float* __restrict__ bk,
    const float* __restrict__ Wv, const float* __restrict__ bv)
{
    int w = blockIdx.z;
    const float* W    = (w==0)?Wq:((w==1)?Wk:Wv);
    const float* bias = (w==0)?bq:((w==1)?bk:bv);
    float* Out        = (w==0)?g_Q:((w==1)?g_K:g_V);

    int m0 = blockIdx.y * 64;
    int n0 = blockIdx.x * 64;
    int tid = threadIdx.x;
    int tx = tid & 15, ty = tid >> 4;

    __shared__ float As[64][17];
    __shared__ float Bs[64][17];
    float acc[4][4] = {};

    for (int kb = 0; kb < DM; kb += 16) {
        #pragma unroll
        for (int r = 0; r < 4; r++) {
            int e = tid + 256*r;
            int row = e >> 4, col = e & 15;
            As[row][col] = X[(m0+row)*DM + kb + col];
            Bs[row][col] = W[(n0+row)*DM + kb + col];
        }
        __syncthreads();
        #pragma unroll
        for (int kk = 0; kk < 16; kk++) {
            float a[4], b[4];
            #pragma unroll
            for (int i=0;i<4;i++) a[i] = As[ty*4+i][kk];
            #pragma unroll
            for (int j=0;j<4;j++) b[j] = Bs[tx*4+j][kk];
            #pragma unroll
            for (int i=0;i<4;i++)
                #pragma unroll
                for (int j=0;j<4;j++) acc[i][j] += a[i]*b[j];
        }
        __syncthreads();
    }

    #pragma unroll
    for (int i=0;i<4;i++){
        int ig = m0 + ty*4 + i;                 // global row in [0, B*S)
        int b_ = ig >> 11, s_ = ig & (SEQ-1);
        #pragma unroll
        for (int j=0;j<4;j++){
            int jg = n0 + tx*4 + j;             // global col in [0, 768)
            int h_ = jg / HD, d_ = jg % HD;
            Out[((b_*NH + h_)*SEQ + s_)*HD + d_] = acc[i][j] + bias[jg];
        }
    }
}

// ============================================================
// K2: scores = Q @ K^T / 20, causal + pad mask, lower-tri tiles only
// ============================================================
__global__ __launch_bounds__(256) void k_scores(const unsigned char* __restrict__ am)
{
    int bh = blockIdx.y;
    int b_ = bh >> 2;
    int t  = blockIdx.x;
    // map linear tri index -> (qt, kt), kt <= qt
    int qt = (int)floorf((sqrtf(8.0f*(float)t + 1.0f) - 1.0f) * 0.5f);
    while ((qt+1)*(qt+2)/2 <= t) ++qt;
    while (qt*(qt+1)/2 > t)      --qt;
    int kt = t - qt*(qt+1)/2;

    int q0 = qt*64, k0 = kt*64;
    const float* Qp = g_Q + (size_t)bh*SEQ*HD;
    const float* Kp = g_K + (size_t)bh*SEQ*HD;

    int tid = threadIdx.x;
    int tx = tid & 15, ty = tid >> 4;

    __shared__ float As[64][17];
    __shared__ float Bs[64][17];
    float acc[4][4] = {};

    for (int kb = 0; kb < HD; kb += 16) {
        #pragma unroll
        for (int r = 0; r < 4; r++) {
            int e = tid + 256*r;
            int row = e >> 4, col = e & 15;
            As[row][col] = Qp[(q0+row)*HD + kb + col];
            Bs[row][col] = Kp[(k0+row)*HD + kb + col];
        }
        __syncthreads();
        #pragma unroll
        for (int kk = 0; kk < 16; kk++) {
            float a[4], b[4];
            #pragma unroll
            for (int i=0;i<4;i++) a[i] = As[ty*4+i][kk];
            #pragma unroll
            for (int j=0;j<4;j++) b[j] = Bs[tx*4+j][kk];
            #pragma unroll
            for (int i=0;i<4;i++)
                #pragma unroll
                for (int j=0;j<4;j++) acc[i][j] += a[i]*b[j];
        }
        __syncthreads();
    }

    #pragma unroll
    for (int i=0;i<4;i++){
        int q = q0 + ty*4 + i;
        bool pad = am[b_*SEQ + q] != 0;
        #pragma unroll
        for (int j=0;j<4;j++){
            int k = k0 + tx*4 + j;
            float v = (k > q || pad) ? NEGV : acc[i][j]*0.05f;
            g_Sc[((long long)(bh*SEQ + q))*SEQ + k] = v;
        }
    }
}

// ============================================================
// K3: per-key-column online (max, sum of exp).  One block per (kt, bh).
// ============================================================
__global__ __launch_bounds__(256) void k_stats()
{
    int kt = blockIdx.x, bh = blockIdx.y;
    int tid = threadIdx.x;
    int kx = tid & 63, qg = tid >> 6;       // 64 columns x 4 q-strides
    int k = kt*64 + kx;

    float m = -3.4e38f, l = 0.0f;
    for (int q = kt*64 + qg; q < SEQ; q += 4) {
        float s = g_Sc[((long long)(bh*SEQ + q))*SEQ + k];
        if (s > m) { l = l*__expf(m - s) + 1.0f; m = s; }
        else       { l += __expf(s - m); }
    }

    __shared__ float sm[4][64], sl[4][64];
    sm[qg][kx] = m; sl[qg][kx] = l;
    __syncthreads();
    if (qg == 0) {
        float M = m, L = l;
        #pragma unroll
        for (int g = 1; g < 4; g++) {
            float mg = sm[g][kx], lg = sl[g][kx];
            float Mn = fmaxf(M, mg);
            L = L*__expf(M - Mn) + lg*__expf(mg - Mn);
            M = Mn;
        }
        g_cm[bh*SEQ + k] = M;
        g_ci[bh*SEQ + k] = 1.0f / L;
    }
}

// ============================================================
// K4: X1 = P @ V, P computed on the fly from raw scores.
// Block: 64 q-rows x full 192 d-cols (exp + score read happen once).
// ============================================================
__global__ __launch_bounds__(256) void k_av()
{
    int qt = (SEQ/64 - 1) - blockIdx.x;     // longest blocks first
    int bh = blockIdx.y;
    int q0 = qt*64;
    int kmax = (qt+1)*64;

    const float* Vp = g_V + (size_t)bh*SEQ*HD;
    const float* cm = g_cm + bh*SEQ;
    const float* ci = g_ci + bh*SEQ;

    int tid = threadIdx.x;
    int tx = tid & 15, ty = tid >> 4;       // cols tx*12..+11, rows ty*4..+3

    __shared__ float Ps[64][17];
    __shared__ float Vs[16][193];
    float acc[4][12] = {};

    for (int k0 = 0; k0 < kmax; k0 += 16) {
        // load P tile (64 q x 16 k), applying exp/normalize inline
        #pragma unroll
        for (int r = 0; r < 4; r++) {
            int e = tid + 256*r;
            int row = e >> 4, col = e & 15;
            int k = k0 + col;
            float s = g_Sc[((long long)(bh*SEQ + q0 + row))*SEQ + k];
            Ps[row][col] = __expf(s - __ldg(&cm[k])) * __ldg(&ci[k]);
        }
        // load V tile (16 k x 192 d)
        #pragma unroll
        for (int r = 0; r < 12; r++) {
            int e = tid + 256*r;
            int vr = e / 192, vc = e - vr*192;
            Vs[vr][vc] = Vp[(k0+vr)*HD + vc];
        }
        __syncthreads();
        #pragma unroll
        for (int kk = 0; kk < 16; kk++) {
            float a[4];
            #pragma unroll
            for (int i=0;i<4;i++) a[i] = Ps[ty*4+i][kk];
            #pragma unroll
            for (int j=0;j<12;j++) {
                float bv = Vs[kk][tx*12+j];
                #pragma unroll
                for (int i=0;i<4;i++) acc[i][j] += a[i]*bv;
            }
        }
        __syncthreads();
    }

    #pragma unroll
    for (int i=0;i<4;i++){
        int q = q0 + ty*4 + i;
        #pragma unroll
        for (int j=0;j<12;j++){
            g_X1[(bh*SEQ + q)*HD + tx*12 + j] = acc[i][j];
        }
    }
}

// ============================================================
// K5: y = x + X1 (re-gathered), LayerNorm(y) * gamma + beta
// ============================================================
__global__ __launch_bounds__(256) void k_ln(
    const float* __restrict__ x,
    const float* __restrict__ gamma,
    const float* __restrict__ beta,
    float* __restrict__ out)
{
    int row = blockIdx.x;
    int b_ = row >> 11, s_ = row & (SEQ-1);
    int tid = threadIdx.x;

    __shared__ float ybuf[DM];
    __shared__ float rs[32], rq[32];
    __shared__ float s_mu, s_inv;

    float sum = 0.0f, sq = 0.0f;
    for (int c = tid; c < DM; c += 256) {
        int h_ = c / HD, d_ = c - h_*HD;
        float v = x[row*DM + c] + g_X1[((b_*NH + h_)*SEQ + s_)*HD + d_];
        ybuf[c] = v;
        sum += v; sq += v*v;
    }
    #pragma unroll
    for (int o = 16; o; o >>= 1) {
        sum += __shfl_down_sync(0xffffffffu, sum, o);
        sq  += __shfl_down_sync(0xffffffffu, sq , o);
    }
    int wid = tid >> 5, lane = tid & 31;
    if (lane == 0) { rs[wid] = sum; rq[wid] = sq; }
    __syncthreads();
    if (tid < 32) {
        sum = (tid < 8) ? rs[tid] : 0.0f;
        sq  = (tid < 8) ? rq[tid] : 0.0f;
        #pragma unroll
        for (int o = 4; o; o >>= 1) {
            sum += __shfl_down_sync(0xffffffffu, sum, o);
            sq  += __shfl_down_sync(0xffffffffu, sq , o);
        }
        if (tid == 0) {
            float mu  = sum * (1.0f/DM);
            float var = sq  * (1.0f/DM) - mu*mu;
            s_mu = mu;
            s_inv = rsqrtf(var + 1e-5f);
        }
    }
    __syncthreads();
    float mu = s_mu, inv = s_inv;
    for (int c = tid; c < DM; c += 256)
        out[row*DM + c] = (ybuf[c] - mu)*inv*gamma[c] + beta[c];
}

// ============================================================
extern "C" void kernel_launch(void* const* d_in, const int* in_sizes, int n_in,
                              void* d_out, int out_size)
{
    const float*         x     = (const float*)d_in[0];
    const unsigned char* am    = (const unsigned char*)d_in[1];
    const float*         Wq    = (const float*)d_in[2];
    const float*         bq    = (const float*)d_in[3];
    const float*         Wk    = (const float*)d_in[4];
    const float*         bk    = (const float*)d_in[5];
    const float*         Wv    = (const float*)d_in[6];
    const float*         bv    = (const float*)d_in[7];
    const float*         gamma = (const float*)d_in[8];
    const float*         beta  = (const float*)d_in[9];
    float*               out   = (float*)d_out;

    (void)in_sizes; (void)n_in; (void)out_size;

    dim3 g1(DM/64, (BATCH*SEQ)/64, 3);
    k_qkv<<<g1, 256>>>(x, Wq, bq, Wk, bk, Wv, bv);

    const int NT = (SEQ/64)*(SEQ/64 + 1)/2;   // 528 lower-tri tiles
    k_scores<<<dim3(NT, BHT), 256>>>(am);

    k_stats<<<dim3(SEQ/64, BHT), 256>>>();

    k_av<<<dim3(SEQ/64, BHT), 256>>>();

    k_ln<<<BATCH*SEQ, 256>>>(x, gamma, beta, out);
}

// round 3
// speedup vs baseline: 4.0812x; 4.0812x over previous
#include <cuda_runtime.h>
#include <cuda_fp16.h>
#include <math.h>

#define SEQ    2048
#define DM     768
#define NH     4
#define HD     192
#define BATCH  4
#define BHT    16
#define NEGH   (-60000.0f)

// ---- device scratch (allocation-free rule: static __device__ arrays) ----
__device__ __align__(16) __half g_Xh [BATCH*SEQ*DM];     // fp16 x
__device__ __align__(16) __half g_Wh [3*DM*DM];          // fp16 Wq|Wk|Wv
__device__ __align__(16) __half g_Qh [BHT*SEQ*HD];
__device__ __align__(16) __half g_Kh [BHT*SEQ*HD];
__device__ __align__(16) __half g_Vh [BHT*SEQ*HD];
__device__ __align__(16) __half g_Sch[(size_t)BHT*SEQ*SEQ];   // 134MB fp16 scores
__device__ float  g_cm[BHT*SEQ];
__device__ float  g_ci[BHT*SEQ];
__device__ float  g_X1[BHT*SEQ*HD];

// ---------------- MMA helpers ----------------
__device__ __forceinline__ unsigned sptr(const void* p){
    return (unsigned)__cvta_generic_to_shared(p);
}
__device__ __forceinline__ void ldsm4(unsigned r[4], unsigned a){
    asm volatile("ldmatrix.sync.aligned.m8n8.x4.shared.b16 {%0,%1,%2,%3},[%4];\n"
        : "=r"(r[0]),"=r"(r[1]),"=r"(r[2]),"=r"(r[3]) : "r"(a));
}
__device__ __forceinline__ void ldsm4t(unsigned r[4], unsigned a){
    asm volatile("ldmatrix.sync.aligned.m8n8.x4.trans.shared.b16 {%0,%1,%2,%3},[%4];\n"
        : "=r"(r[0]),"=r"(r[1]),"=r"(r[2]),"=r"(r[3]) : "r"(a));
}
__device__ __forceinline__ void mma16816(float* c, const unsigned* a, unsigned b0, unsigned b1){
    asm volatile("mma.sync.aligned.m16n8k16.row.col.f32.f16.f16.f32 "
        "{%0,%1,%2,%3},{%4,%5,%6,%7},{%8,%9},{%0,%1,%2,%3};\n"
        : "+f"(c[0]),"+f"(c[1]),"+f"(c[2]),"+f"(c[3])
        : "r"(a[0]),"r"(a[1]),"r"(a[2]),"r"(a[3]),"r"(b0),"r"(b1));
}

// ---------------- conversions ----------------
__global__ __launch_bounds__(256) void k_cvt_x(const float* __restrict__ x){
    int i = (blockIdx.x*256 + threadIdx.x)*4;
    float4 v = *(const float4*)(x+i);
    __half2 h0 = __floats2half2_rn(v.x,v.y), h1 = __floats2half2_rn(v.z,v.w);
    *(__half2*)&g_Xh[i]   = h0;
    *(__half2*)&g_Xh[i+2] = h1;
}
__global__ __launch_bounds__(256) void k_cvt_w(
    const float* __restrict__ Wq, const float* __restrict__ Wk, const float* __restrict__ Wv){
    int w = blockIdx.y;
    const float* src = (w==0)?Wq:((w==1)?Wk:Wv);
    __half* dst = g_Wh + w*DM*DM;
    int i = (blockIdx.x*256 + threadIdx.x)*4;
    float4 v = *(const float4*)(src+i);
    *(__half2*)&dst[i]   = __floats2half2_rn(v.x,v.y);
    *(__half2*)&dst[i+2] = __floats2half2_rn(v.z,v.w);
}

// ============================================================
// K1: QKV projection GEMM-NT (M=8192, N=2304, K=768), fp16 MMA
// block 128x128, 8 warps (2x4), warp tile 64x32, kc=64
// ============================================================
__global__ __launch_bounds__(256) void k_qkv(
    const float* __restrict__ bq, const float* __restrict__ bk, const float* __restrict__ bv)
{
    const int n0 = blockIdx.x*128, m0 = blockIdx.y*128;
    const int tid = threadIdx.x, lane = tid&31, wid = tid>>5;
    const int wm = wid>>2, wn = wid&3;

    __shared__ __half As[128][72];
    __shared__ __half Bs[128][72];
    float acc[4][4][4] = {};

    const int lrow = lane&15, lcol = (lane>>4)*8;

    for (int kb = 0; kb < DM; kb += 64) {
        #pragma unroll
        for (int i=0;i<4;i++){
            int idx = tid + 256*i;
            int row = idx>>3, vc = idx&7;
            *(uint4*)&As[row][vc*8] = *(const uint4*)&g_Xh[(size_t)(m0+row)*DM + kb + vc*8];
            *(uint4*)&Bs[row][vc*8] = *(const uint4*)&g_Wh[(size_t)(n0+row)*DM + kb + vc*8];
        }
        __syncthreads();
        #pragma unroll
        for (int kk=0;kk<4;kk++){
            unsigned a[4][4], b[2][4];
            #pragma unroll
            for (int mi=0;mi<4;mi++)
                ldsm4(a[mi], sptr(&As[wm*64+mi*16+lrow][kk*16+lcol]));
            #pragma unroll
            for (int np=0;np<2;np++)
                ldsm4(b[np], sptr(&Bs[wn*32+np*16+lrow][kk*16+lcol]));
            #pragma unroll
            for (int mi=0;mi<4;mi++)
                #pragma unroll
                for (int ni=0;ni<4;ni++)
                    mma16816(acc[mi][ni], a[mi], b[ni>>1][ni&1], b[ni>>1][(ni&1)+2]);
        }
        __syncthreads();
    }

    const int w = n0/DM;
    const float* bias = (w==0)?bq:((w==1)?bk:bv);
    __half* Out = (w==0)?g_Qh:((w==1)?g_Kh:g_Vh);

    #pragma unroll
    for (int mi=0;mi<4;mi++){
        int r0 = m0 + wm*64 + mi*16 + (lane>>2);
        #pragma unroll
        for (int ni=0;ni<4;ni++){
            int n = n0 + wn*32 + ni*8 + (lane&3)*2;
            int c = n - w*DM;
            int h = c/HD, d = c - h*HD;
            float b0f = bias[c], b1f = bias[c+1];
            #pragma unroll
            for (int p=0;p<2;p++){
                int m = r0 + p*8;
                int b_ = m>>11, s_ = m&(SEQ-1);
                __half2 hv = __floats2half2_rn(acc[mi][ni][2*p]+b0f, acc[mi][ni][2*p+1]+b1f);
                *(__half2*)&Out[((size_t)((b_*NH+h)*SEQ+s_))*HD + d] = hv;
            }
        }
    }
}

// ============================================================
// K2: scores = Q@K^T/20, causal+pad mask, lower-tri 128x128 tiles, fp16 MMA
// ============================================================
__global__ __launch_bounds__(256) void k_scores(const unsigned char* __restrict__ am)
{
    const int bh = blockIdx.y, b_ = bh>>2;
    int t = blockIdx.x;
    int qt = (int)((sqrtf(8.f*(float)t+1.f)-1.f)*0.5f);
    while ((qt+1)*(qt+2)/2 <= t) ++qt;
    while (qt*(qt+1)/2 > t)      --qt;
    int kt = t - qt*(qt+1)/2;
    const int q0 = qt*128, k0 = kt*128;

    const __half* Qp = g_Qh + (size_t)bh*SEQ*HD;
    const __half* Kp = g_Kh + (size_t)bh*SEQ*HD;
    __half* Sp = g_Sch + (size_t)bh*SEQ*SEQ;

    const int tid = threadIdx.x, lane = tid&31, wid = tid>>5;
    const int wm = wid>>2, wn = wid&3;
    const int lrow = lane&15, lcol = (lane>>4)*8;

    __shared__ __half As[128][72];
    __shared__ __half Bs[128][72];
    float acc[4][4][4] = {};

    for (int kb = 0; kb < HD; kb += 64) {
        #pragma unroll
        for (int i=0;i<4;i++){
            int idx = tid + 256*i;
            int row = idx>>3, vc = idx&7;
            *(uint4*)&As[row][vc*8] = *(const uint4*)&Qp[(size_t)(q0+row)*HD + kb + vc*8];
            *(uint4*)&Bs[row][vc*8] = *(const uint4*)&Kp[(size_t)(k0+row)*HD + kb + vc*8];
        }
        __syncthreads();
        #pragma unroll
        for (int kk=0;kk<4;kk++){
            unsigned a[4][4], b[2][4];
            #pragma unroll
            for (int mi=0;mi<4;mi++)
                ldsm4(a[mi], sptr(&As[wm*64+mi*16+lrow][kk*16+lcol]));
            #pragma unroll
            for (int np=0;np<2;np++)
                ldsm4(b[np], sptr(&Bs[wn*32+np*16+lrow][kk*16+lcol]));
            #pragma unroll
            for (int mi=0;mi<4;mi++)
                #pragma unroll
                for (int ni=0;ni<4;ni++)
                    mma16816(acc[mi][ni], a[mi], b[ni>>1][ni&1], b[ni>>1][(ni&1)+2]);
        }
        __syncthreads();
    }

    #pragma unroll
    for (int mi=0;mi<4;mi++){
        int r0 = q0 + wm*64 + mi*16 + (lane>>2);
        #pragma unroll
        for (int p=0;p<2;p++){
            int q = r0 + p*8;
            bool pad = am[b_*SEQ + q] != 0;
            #pragma unroll
            for (int ni=0;ni<4;ni++){
                int k = k0 + wn*32 + ni*8 + (lane&3)*2;
                float v0 = (k   > q || pad) ? NEGH : acc[mi][ni][2*p]  *0.05f;
                float v1 = (k+1 > q || pad) ? NEGH : acc[mi][ni][2*p+1]*0.05f;
                *(__half2*)&Sp[(size_t)q*SEQ + k] = __floats2half2_rn(v0,v1);
            }
        }
    }
}

// ============================================================
// K3: per-key-column online (max, 1/sum-exp). 128 cols per block.
// ============================================================
__global__ __launch_bounds__(256) void k_stats()
{
    int kt = blockIdx.x, bh = blockIdx.y;
    int tid = threadIdx.x;
    int kx = tid & 127, qg = tid >> 7;
    int k = kt*128 + kx;
    const __half* Sp = g_Sch + (size_t)bh*SEQ*SEQ;

    float m = -1e30f, l = 0.0f;
    for (int q = kt*128 + qg; q < SEQ; q += 2){
        float s = __half2float(Sp[(size_t)q*SEQ + k]);
        if (s > m) { l = l*__expf(m - s) + 1.0f; m = s; }
        else       { l += __expf(s - m); }
    }
    __shared__ float sm[2][128], sl[2][128];
    sm[qg][kx] = m; sl[qg][kx] = l;
    __syncthreads();
    if (qg == 0){
        float m2 = sm[1][kx], l2 = sl[1][kx];
        float M = fmaxf(m, m2);
        float L = l*__expf(m - M) + l2*__expf(m2 - M);
        g_cm[bh*SEQ + k] = M;
        g_ci[bh*SEQ + k] = 1.0f/L;
    }
}

// ============================================================
// K4: X1 = P@V with P = exp(s-m)*ci built on the fly (fp16 MMA)
// block 128(q) x 192(d), 8 warps (2x4), warp tile 64x48, kc=64
// ============================================================
__global__ __launch_bounds__(256) void k_av()
{
    const int qt = (SEQ/128 - 1) - blockIdx.x;   // longest first
    const int bh = blockIdx.y;
    const int q0 = qt*128;
    const int kmax = (qt+1)*128;

    const __half* Vp = g_Vh + (size_t)bh*SEQ*HD;
    const __half* Sp = g_Sch + (size_t)bh*SEQ*SEQ;
    const float* cm = g_cm + bh*SEQ;
    const float* ci = g_ci + bh*SEQ;

    const int tid = threadIdx.x, lane = tid&31, wid = tid>>5;
    const int wm = wid>>2, wn = wid&3;
    const int lrow = lane&15, lcol = (lane>>4)*8;

    __shared__ __half Ps[128][72];
    __shared__ __half Vs[64][200];
    float acc[4][6][4] = {};

    for (int k0 = 0; k0 < kmax; k0 += 64) {
        // build P tile (exp+normalize inline)
        #pragma unroll
        for (int i=0;i<4;i++){
            int idx = tid + 256*i;
            int row = idx>>3, vc = idx&7;
            uint4 raw = *(const uint4*)&Sp[(size_t)(q0+row)*SEQ + k0 + vc*8];
            __half2* hp = (__half2*)&raw;
            __half2 o[4];
            #pragma unroll
            for (int j=0;j<4;j++){
                float2 f = __half22float2(hp[j]);
                int kk2 = k0 + vc*8 + j*2;
                float e0 = __expf(f.x - __ldg(&cm[kk2]))   * __ldg(&ci[kk2]);
                float e1 = __expf(f.y - __ldg(&cm[kk2+1])) * __ldg(&ci[kk2+1]);
                o[j] = __floats2half2_rn(e0,e1);
            }
            *(uint4*)&Ps[row][vc*8] = *(uint4*)o;
        }
        // V tile 64x192
        #pragma unroll
        for (int i=0;i<6;i++){
            int idx = tid + 256*i;
            int row = idx/24, vc = idx%24;
            *(uint4*)&Vs[row][vc*8] = *(const uint4*)&Vp[(size_t)(k0+row)*HD + vc*8];
        }
        __syncthreads();
        #pragma unroll
        for (int kk=0;kk<4;kk++){
            unsigned a[4][4], b[3][4];
            #pragma unroll
            for (int mi=0;mi<4;mi++)
                ldsm4(a[mi], sptr(&Ps[wm*64+mi*16+lrow][kk*16+lcol]));
            #pragma unroll
            for (int np=0;np<3;np++)
                ldsm4t(b[np], sptr(&Vs[kk*16+lrow][wn*48+np*16+lcol]));
            #pragma unroll
            for (int mi=0;mi<4;mi++)
                #pragma unroll
                for (int ni=0;ni<6;ni++)
                    mma16816(acc[mi][ni], a[mi], b[ni>>1][(ni&1)*2], b[ni>>1][(ni&1)*2+1]);
        }
        __syncthreads();
    }

    #pragma unroll
    for (int mi=0;mi<4;mi++){
        int r0 = q0 + wm*64 + mi*16 + (lane>>2);
        #pragma unroll
        for (int ni=0;ni<6;ni++){
            int d = wn*48 + ni*8 + (lane&3)*2;
            #pragma unroll
            for (int p=0;p<2;p++){
                int q = r0 + p*8;
                float2 v = make_float2(acc[mi][ni][2*p], acc[mi][ni][2*p+1]);
                *(float2*)&g_X1[((size_t)(bh*SEQ+q))*HD + d] = v;
            }
        }
    }
}

// ============================================================
// K5: y = x + X1, LayerNorm
// ============================================================
__global__ __launch_bounds__(256) void k_ln(
    const float* __restrict__ x,
    const float* __restrict__ gamma,
    const float* __restrict__ beta,
    float* __restrict__ out)
{
    int row = blockIdx.x;
    int b_ = row >> 11, s_ = row & (SEQ-1);
    int tid = threadIdx.x;

    __shared__ float ybuf[DM];
    __shared__ float rs[32], rq[32];
    __shared__ float s_mu, s_inv;

    float sum = 0.0f, sq = 0.0f;
    for (int c = tid; c < DM; c += 256){
        int h_ = c/HD, d_ = c - h_*HD;
        float v = x[(size_t)row*DM + c] + g_X1[((size_t)((b_*NH+h_)*SEQ+s_))*HD + d_];
        ybuf[c] = v;
        sum += v; sq += v*v;
    }
    #pragma unroll
    for (int o = 16; o; o >>= 1){
        sum += __shfl_down_sync(0xffffffffu, sum, o);
        sq  += __shfl_down_sync(0xffffffffu, sq , o);
    }
    int wid = tid >> 5, lane = tid & 31;
    if (lane == 0){ rs[wid] = sum; rq[wid] = sq; }
    __syncthreads();
    if (tid < 32){
        sum = (tid < 8) ? rs[tid] : 0.0f;
        sq  = (tid < 8) ? rq[tid] : 0.0f;
        #pragma unroll
        for (int o = 4; o; o >>= 1){
            sum += __shfl_down_sync(0xffffffffu, sum, o);
            sq  += __shfl_down_sync(0xffffffffu, sq , o);
        }
        if (tid == 0){
            float mu  = sum * (1.0f/DM);
            float var = sq  * (1.0f/DM) - mu*mu;
            s_mu = mu;
            s_inv = rsqrtf(var + 1e-5f);
        }
    }
    __syncthreads();
    float mu = s_mu, inv = s_inv;
    for (int c = tid; c < DM; c += 256)
        out[(size_t)row*DM + c] = (ybuf[c] - mu)*inv*gamma[c] + beta[c];
}

// ============================================================
extern "C" void kernel_launch(void* const* d_in, const int* in_sizes, int n_in,
                              void* d_out, int out_size)
{
    const float*         x     = (const float*)d_in[0];
    const unsigned char* am    = (const unsigned char*)d_in[1];
    const float*         Wq    = (const float*)d_in[2];
    const float*         bq    = (const float*)d_in[3];
    const float*         Wk    = (const float*)d_in[4];
    const float*         bk    = (const float*)d_in[5];
    const float*         Wv    = (const float*)d_in[6];
    const float*         bv    = (const float*)d_in[7];
    const float*         gamma = (const float*)d_in[8];
    const float*         beta  = (const float*)d_in[9];
    float*               out   = (float*)d_out;
    (void)in_sizes; (void)n_in; (void)out_size;

    k_cvt_x<<<BATCH*SEQ*DM/1024, 256>>>(x);
    k_cvt_w<<<dim3(DM*DM/1024, 3), 256>>>(Wq, Wk, Wv);

    k_qkv<<<dim3(3*DM/128, BATCH*SEQ/128), 256>>>(bq, bk, bv);

    const int NT = (SEQ/128)*(SEQ/128 + 1)/2;   // 136 lower-tri tiles
    k_scores<<<dim3(NT, BHT), 256>>>(am);

    k_stats<<<dim3(SEQ/128, BHT), 256>>>();

    k_av<<<dim3(SEQ/128, BHT), 256>>>();

    k_ln<<<BATCH*SEQ, 256>>>(x, gamma, beta, out);
}

// round 4
// speedup vs baseline: 6.3071x; 1.5454x over previous
#include <cuda_runtime.h>
#include <cuda_fp16.h>
#include <math.h>

#define SEQ    2048
#define DM     768
#define NH     4
#define HD     192
#define BATCH  4
#define BHT    16
#define NEGH   (-60000.0f)

// ---- device scratch ----
__device__ __align__(16) __half g_Xh [BATCH*SEQ*DM];
__device__ __align__(16) __half g_Wh [3*DM*DM];
__device__ __align__(16) __half g_Qh [BHT*SEQ*HD];
__device__ __align__(16) __half g_Kh [BHT*SEQ*HD];
__device__ __align__(16) __half g_Vh [BHT*SEQ*HD];
__device__ __align__(16) __half g_Sch[(size_t)BHT*SEQ*SEQ];
__device__ float  g_pm[BHT*16*SEQ];     // per-(bh,qt,k) partial max
__device__ float  g_pl[BHT*16*SEQ];     // per-(bh,qt,k) partial sum
__device__ float  g_cm[BHT*SEQ];
__device__ float  g_ci[BHT*SEQ];
__device__ float  g_X1[BHT*SEQ*HD];

// ---------------- helpers ----------------
__device__ __forceinline__ unsigned sptr(const void* p){
    return (unsigned)__cvta_generic_to_shared(p);
}
__device__ __forceinline__ void cpa16(unsigned dst, const void* src){
    asm volatile("cp.async.cg.shared.global [%0], [%1], 16;\n" :: "r"(dst), "l"(src));
}
__device__ __forceinline__ void cpa_commit(){ asm volatile("cp.async.commit_group;\n"); }
__device__ __forceinline__ void cpa_wait_all(){ asm volatile("cp.async.wait_group 0;\n"); }

__device__ __forceinline__ void ldsm4(unsigned r[4], unsigned a){
    asm volatile("ldmatrix.sync.aligned.m8n8.x4.shared.b16 {%0,%1,%2,%3},[%4];\n"
        : "=r"(r[0]),"=r"(r[1]),"=r"(r[2]),"=r"(r[3]) : "r"(a));
}
__device__ __forceinline__ void ldsm4t(unsigned r[4], unsigned a){
    asm volatile("ldmatrix.sync.aligned.m8n8.x4.trans.shared.b16 {%0,%1,%2,%3},[%4];\n"
        : "=r"(r[0]),"=r"(r[1]),"=r"(r[2]),"=r"(r[3]) : "r"(a));
}
__device__ __forceinline__ void mma16816(float* c, const unsigned* a, unsigned b0, unsigned b1){
    asm volatile("mma.sync.aligned.m16n8k16.row.col.f32.f16.f16.f32 "
        "{%0,%1,%2,%3},{%4,%5,%6,%7},{%8,%9},{%0,%1,%2,%3};\n"
        : "+f"(c[0]),"+f"(c[1]),"+f"(c[2]),"+f"(c[3])
        : "r"(a[0]),"r"(a[1]),"r"(a[2]),"r"(a[3]),"r"(b0),"r"(b1));
}

// ---------------- conversions ----------------
__global__ __launch_bounds__(256) void k_cvt_x(const float* __restrict__ x){
    int i = (blockIdx.x*256 + threadIdx.x)*4;
    float4 v = *(const float4*)(x+i);
    *(__half2*)&g_Xh[i]   = __floats2half2_rn(v.x,v.y);
    *(__half2*)&g_Xh[i+2] = __floats2half2_rn(v.z,v.w);
}
__global__ __launch_bounds__(256) void k_cvt_w(
    const float* __restrict__ Wq, const float* __restrict__ Wk, const float* __restrict__ Wv){
    int w = blockIdx.y;
    const float* src = (w==0)?Wq:((w==1)?Wk:Wv);
    __half* dst = g_Wh + w*DM*DM;
    int i = (blockIdx.x*256 + threadIdx.x)*4;
    float4 v = *(const float4*)(src+i);
    *(__half2*)&dst[i]   = __floats2half2_rn(v.x,v.y);
    *(__half2*)&dst[i+2] = __floats2half2_rn(v.z,v.w);
}

// ============================================================
// K1: QKV projection GEMM-NT, cp.async double-buffered
// ============================================================
__global__ __launch_bounds__(256,2) void k_qkv(
    const float* __restrict__ bq, const float* __restrict__ bk, const float* __restrict__ bv)
{
    extern __shared__ __align__(16) char smraw[];
    __half* As = (__half*)smraw;            // [2][128][72]
    __half* Bs = As + 2*128*72;             // [2][128][72]

    const int n0 = blockIdx.x*128, m0 = blockIdx.y*128;
    const int tid = threadIdx.x, lane = tid&31, wid = tid>>5;
    const int wm = wid>>2, wn = wid&3;
    const int lrow = lane&15, lcol = (lane>>4)*8;

    float acc[4][4][4] = {};

    const int ldr = tid>>3, ldc = (tid&7)*8;

    // prefetch stage 0
    #pragma unroll
    for (int i=0;i<4;i++){
        int row = ldr + 32*i;
        cpa16(sptr(&As[(size_t)row*72 + ldc]), &g_Xh[(size_t)(m0+row)*DM + ldc]);
        cpa16(sptr(&Bs[(size_t)row*72 + ldc]), &g_Wh[(size_t)(n0+row)*DM + ldc]);
    }
    cpa_commit();

    const int NIT = DM/64;
    for (int it=0; it<NIT; it++){
        int cur = it & 1;
        cpa_wait_all();
        __syncthreads();
        if (it+1 < NIT){
            int nb = (it+1)&1, kb = (it+1)*64;
            #pragma unroll
            for (int i=0;i<4;i++){
                int row = ldr + 32*i;
                cpa16(sptr(&As[(size_t)(nb*128+row)*72 + ldc]), &g_Xh[(size_t)(m0+row)*DM + kb + ldc]);
                cpa16(sptr(&Bs[(size_t)(nb*128+row)*72 + ldc]), &g_Wh[(size_t)(n0+row)*DM + kb + ldc]);
            }
            cpa_commit();
        }
        const __half* Ab = As + (size_t)cur*128*72;
        const __half* Bb = Bs + (size_t)cur*128*72;
        #pragma unroll
        for (int kk=0;kk<4;kk++){
            unsigned a[4][4], b[2][4];
            #pragma unroll
            for (int mi=0;mi<4;mi++)
                ldsm4(a[mi], sptr(&Ab[(size_t)(wm*64+mi*16+lrow)*72 + kk*16+lcol]));
            #pragma unroll
            for (int np=0;np<2;np++)
                ldsm4(b[np], sptr(&Bb[(size_t)(wn*32+np*16+lrow)*72 + kk*16+lcol]));
            #pragma unroll
            for (int mi=0;mi<4;mi++)
                #pragma unroll
                for (int ni=0;ni<4;ni++)
                    mma16816(acc[mi][ni], a[mi], b[ni>>1][ni&1], b[ni>>1][(ni&1)+2]);
        }
        __syncthreads();
    }

    const int w = n0/DM;
    const float* bias = (w==0)?bq:((w==1)?bk:bv);
    __half* Out = (w==0)?g_Qh:((w==1)?g_Kh:g_Vh);

    #pragma unroll
    for (int mi=0;mi<4;mi++){
        int r0 = m0 + wm*64 + mi*16 + (lane>>2);
        #pragma unroll
        for (int ni=0;ni<4;ni++){
            int n = n0 + wn*32 + ni*8 + (lane&3)*2;
            int c = n - w*DM;
            int h = c/HD, d = c - h*HD;
            float b0f = bias[c], b1f = bias[c+1];
            #pragma unroll
            for (int p=0;p<2;p++){
                int m = r0 + p*8;
                int b_ = m>>11, s_ = m&(SEQ-1);
                __half2 hv = __floats2half2_rn(acc[mi][ni][2*p]+b0f, acc[mi][ni][2*p+1]+b1f);
                *(__half2*)&Out[((size_t)((b_*NH+h)*SEQ+s_))*HD + d] = hv;
            }
        }
    }
}

// ============================================================
// K2: scores + fused per-tile column stats (lower-tri 128x128)
// ============================================================
__global__ __launch_bounds__(256,2) void k_scores(const unsigned char* __restrict__ am)
{
    extern __shared__ __align__(16) char smraw[];
    __half* As = (__half*)smraw;            // [2][128][72]
    __half* Bs = As + 2*128*72;
    float*  pm = (float*)(Bs + 2*128*72);   // [2][128]
    float*  pl = pm + 256;

    const int bh = blockIdx.y, b_ = bh>>2;
    int t = blockIdx.x;
    int qt = (int)((sqrtf(8.f*(float)t+1.f)-1.f)*0.5f);
    while ((qt+1)*(qt+2)/2 <= t) ++qt;
    while (qt*(qt+1)/2 > t)      --qt;
    int kt = t - qt*(qt+1)/2;
    const int q0 = qt*128, k0 = kt*128;

    const __half* Qp = g_Qh + (size_t)bh*SEQ*HD;
    const __half* Kp = g_Kh + (size_t)bh*SEQ*HD;
    __half* Sp = g_Sch + (size_t)bh*SEQ*SEQ;

    const int tid = threadIdx.x, lane = tid&31, wid = tid>>5;
    const int wm = wid>>2, wn = wid&3;
    const int lrow = lane&15, lcol = (lane>>4)*8;
    const int ldr = tid>>3, ldc = (tid&7)*8;

    float acc[4][4][4] = {};

    #pragma unroll
    for (int i=0;i<4;i++){
        int row = ldr + 32*i;
        cpa16(sptr(&As[(size_t)row*72 + ldc]), &Qp[(size_t)(q0+row)*HD + ldc]);
        cpa16(sptr(&Bs[(size_t)row*72 + ldc]), &Kp[(size_t)(k0+row)*HD + ldc]);
    }
    cpa_commit();

    const int NIT = HD/64;
    for (int it=0; it<NIT; it++){
        int cur = it & 1;
        cpa_wait_all();
        __syncthreads();
        if (it+1 < NIT){
            int nb = (it+1)&1, kb = (it+1)*64;
            #pragma unroll
            for (int i=0;i<4;i++){
                int row = ldr + 32*i;
                cpa16(sptr(&As[(size_t)(nb*128+row)*72 + ldc]), &Qp[(size_t)(q0+row)*HD + kb + ldc]);
                cpa16(sptr(&Bs[(size_t)(nb*128+row)*72 + ldc]), &Kp[(size_t)(k0+row)*HD + kb + ldc]);
            }
            cpa_commit();
        }
        const __half* Ab = As + (size_t)cur*128*72;
        const __half* Bb = Bs + (size_t)cur*128*72;
        #pragma unroll
        for (int kk=0;kk<4;kk++){
            unsigned a[4][4], b[2][4];
            #pragma unroll
            for (int mi=0;mi<4;mi++)
                ldsm4(a[mi], sptr(&Ab[(size_t)(wm*64+mi*16+lrow)*72 + kk*16+lcol]));
            #pragma unroll
            for (int np=0;np<2;np++)
                ldsm4(b[np], sptr(&Bb[(size_t)(wn*32+np*16+lrow)*72 + kk*16+lcol]));
            #pragma unroll
            for (int mi=0;mi<4;mi++)
                #pragma unroll
                for (int ni=0;ni<4;ni++)
                    mma16816(acc[mi][ni], a[mi], b[ni>>1][ni&1], b[ni>>1][(ni&1)+2]);
        }
        __syncthreads();
    }

    // ---- epilogue: store masked fp16 scores + online column stats ----
    float colm[4][2], coll[4][2];
    #pragma unroll
    for (int ni=0;ni<4;ni++){ colm[ni][0]=colm[ni][1]=-1e30f; coll[ni][0]=coll[ni][1]=0.f; }

    #pragma unroll
    for (int mi=0;mi<4;mi++){
        int r0 = q0 + wm*64 + mi*16 + (lane>>2);
        #pragma unroll
        for (int p=0;p<2;p++){
            int q = r0 + p*8;
            bool pad = am[b_*SEQ + q] != 0;
            #pragma unroll
            for (int ni=0;ni<4;ni++){
                int k = k0 + wn*32 + ni*8 + (lane&3)*2;
                float v0 = (k   > q || pad) ? NEGH : acc[mi][ni][2*p]  *0.05f;
                float v1 = (k+1 > q || pad) ? NEGH : acc[mi][ni][2*p+1]*0.05f;
                __half2 h2 = __floats2half2_rn(v0,v1);
                *(__half2*)&Sp[(size_t)q*SEQ + k] = h2;
                float2 f = __half22float2(h2);
                float M0 = fmaxf(colm[ni][0], f.x);
                coll[ni][0] = coll[ni][0]*__expf(colm[ni][0]-M0) + __expf(f.x-M0);
                colm[ni][0] = M0;
                float M1 = fmaxf(colm[ni][1], f.y);
                coll[ni][1] = coll[ni][1]*__expf(colm[ni][1]-M1) + __expf(f.y-M1);
                colm[ni][1] = M1;
            }
        }
    }
    // reduce across the 8 row-groups of the warp (xor 4/8/16 keeps lane&3)
    #pragma unroll
    for (int off=4; off<32; off<<=1){
        #pragma unroll
        for (int ni=0;ni<4;ni++){
            #pragma unroll
            for (int c=0;c<2;c++){
                float om = __shfl_xor_sync(0xffffffffu, colm[ni][c], off);
                float ol = __shfl_xor_sync(0xffffffffu, coll[ni][c], off);
                float M = fmaxf(colm[ni][c], om);
                coll[ni][c] = coll[ni][c]*__expf(colm[ni][c]-M) + ol*__expf(om-M);
                colm[ni][c] = M;
            }
        }
    }
    if (lane < 4){
        #pragma unroll
        for (int ni=0;ni<4;ni++){
            #pragma unroll
            for (int c=0;c<2;c++){
                int col = wn*32 + ni*8 + lane*2 + c;
                pm[wm*128 + col] = colm[ni][c];
                pl[wm*128 + col] = coll[ni][c];
            }
        }
    }
    __syncthreads();
    if (tid < 128){
        float m0 = pm[tid], m1 = pm[128+tid];
        float l0 = pl[tid], l1 = pl[128+tid];
        float M = fmaxf(m0, m1);
        float L = l0*__expf(m0-M) + l1*__expf(m1-M);
        size_t o = ((size_t)(bh*16 + qt))*SEQ + k0 + tid;
        g_pm[o] = M;
        g_pl[o] = L;
    }
}

// ============================================================
// K3: reduce column partials over qt -> cm, ci
// ============================================================
__global__ __launch_bounds__(256) void k_red()
{
    int idx = blockIdx.x*256 + threadIdx.x;     // over BHT*SEQ
    int bh = idx >> 11;
    int k  = idx & (SEQ-1);
    int kt = k >> 7;
    float m = -1e30f, l = 0.f;
    for (int qt = kt; qt < 16; qt++){
        size_t o = ((size_t)(bh*16 + qt))*SEQ + k;
        float pmv = g_pm[o], plv = g_pl[o];
        float M = fmaxf(m, pmv);
        l = l*__expf(m-M) + plv*__expf(pmv-M);
        m = M;
    }
    g_cm[idx] = m;
    g_ci[idx] = 1.0f/l;
}

// ============================================================
// K4: X1 = P@V, cp.async staged scores+V, exp transform in smem
// ============================================================
__global__ __launch_bounds__(256,2) void k_av()
{
    extern __shared__ __align__(16) char smraw[];
    __half* Ss = (__half*)smraw;            // [2][128][64]
    __half* Vs = Ss + 2*128*64;             // [2][64][200]
    __half* Ps = Vs + 2*64*200;             // [128][72]

    const int qt = (SEQ/128 - 1) - blockIdx.x;
    const int bh = blockIdx.y;
    const int q0 = qt*128;
    const int kmax = (qt+1)*128;

    const __half* Vp = g_Vh + (size_t)bh*SEQ*HD;
    const __half* Sp = g_Sch + (size_t)bh*SEQ*SEQ;
    const float* cm = g_cm + bh*SEQ;
    const float* ci = g_ci + bh*SEQ;

    const int tid = threadIdx.x, lane = tid&31, wid = tid>>5;
    const int wm = wid>>2, wn = wid&3;
    const int lrow = lane&15, lcol = (lane>>4)*8;

    float acc[4][6][4] = {};

    const int srow = tid>>3, svc = (tid&7)*8;   // score tile: 128 rows x 8 chunks
    const int vrow6 = tid/24, vvc6 = (tid%24)*8;

    // prefetch stage 0
    {
        #pragma unroll
        for (int i=0;i<4;i++){
            int row = srow + 32*i;
            cpa16(sptr(&Ss[(size_t)row*64 + svc]), &Sp[(size_t)(q0+row)*SEQ + svc]);
        }
        #pragma unroll
        for (int i=0;i<6;i++){
            int idx = tid + 256*i;
            int row = idx/24, vc = (idx%24)*8;
            cpa16(sptr(&Vs[(size_t)row*200 + vc]), &Vp[(size_t)row*HD + vc]);
        }
        cpa_commit();
    }

    const int NIT = kmax >> 6;
    for (int it=0; it<NIT; it++){
        int cur = it & 1;
        cpa_wait_all();
        __syncthreads();
        if (it+1 < NIT){
            int nb = (it+1)&1, kb = (it+1)*64;
            #pragma unroll
            for (int i=0;i<4;i++){
                int row = srow + 32*i;
                cpa16(sptr(&Ss[(size_t)(nb*128+row)*64 + svc]), &Sp[(size_t)(q0+row)*SEQ + kb + svc]);
            }
            #pragma unroll
            for (int i=0;i<6;i++){
                int idx = tid + 256*i;
                int row = idx/24, vc = (idx%24)*8;
                cpa16(sptr(&Vs[(size_t)(nb*64+row)*200 + vc]), &Vp[(size_t)(kb+row)*HD + vc]);
            }
            cpa_commit();
        }
        // transform: Ss[cur] -> Ps (exp+normalize)
        const __half* Sb = Ss + (size_t)cur*128*64;
        int kbase = it*64;
        #pragma unroll
        for (int i=0;i<4;i++){
            int row = srow + 32*i;
            uint4 raw = *(const uint4*)&Sb[(size_t)row*64 + svc];
            __half2* hp = (__half2*)&raw;
            __half2 o[4];
            #pragma unroll
            for (int j=0;j<4;j++){
                float2 f = __half22float2(hp[j]);
                int k2 = kbase + svc + j*2;
                float e0 = __expf(f.x - __ldg(&cm[k2]))   * __ldg(&ci[k2]);
                float e1 = __expf(f.y - __ldg(&cm[k2+1])) * __ldg(&ci[k2+1]);
                o[j] = __floats2half2_rn(e0,e1);
            }
            *(uint4*)&Ps[(size_t)row*72 + svc] = *(uint4*)o;
        }
        __syncthreads();
        // MMA
        const __half* Vb = Vs + (size_t)cur*64*200;
        #pragma unroll
        for (int kk=0;kk<4;kk++){
            unsigned a[4][4], b[3][4];
            #pragma unroll
            for (int mi=0;mi<4;mi++)
                ldsm4(a[mi], sptr(&Ps[(size_t)(wm*64+mi*16+lrow)*72 + kk*16+lcol]));
            #pragma unroll
            for (int np=0;np<3;np++)
                ldsm4t(b[np], sptr(&Vb[(size_t)(kk*16+lrow)*200 + wn*48+np*16+lcol]));
            #pragma unroll
            for (int mi=0;mi<4;mi++)
                #pragma unroll
                for (int ni=0;ni<6;ni++)
                    mma16816(acc[mi][ni], a[mi], b[ni>>1][(ni&1)*2], b[ni>>1][(ni&1)*2+1]);
        }
    }

    #pragma unroll
    for (int mi=0;mi<4;mi++){
        int r0 = q0 + wm*64 + mi*16 + (lane>>2);
        #pragma unroll
        for (int ni=0;ni<6;ni++){
            int d = wn*48 + ni*8 + (lane&3)*2;
            #pragma unroll
            for (int p=0;p<2;p++){
                int q = r0 + p*8;
                *(float2*)&g_X1[((size_t)(bh*SEQ+q))*HD + d] =
                    make_float2(acc[mi][ni][2*p], acc[mi][ni][2*p+1]);
            }
        }
    }
}

// ============================================================
// K5: y = x + X1, LayerNorm
// ============================================================
__global__ __launch_bounds__(256) void k_ln(
    const float* __restrict__ x,
    const float* __restrict__ gamma,
    const float* __restrict__ beta,
    float* __restrict__ out)
{
    int row = blockIdx.x;
    int b_ = row >> 11, s_ = row & (SEQ-1);
    int tid = threadIdx.x;

    __shared__ float ybuf[DM];
    __shared__ float rs[32], rq[32];
    __shared__ float s_mu, s_inv;

    float sum = 0.0f, sq = 0.0f;
    for (int c = tid; c < DM; c += 256){
        int h_ = c/HD, d_ = c - h_*HD;
        float v = x[(size_t)row*DM + c] + g_X1[((size_t)((b_*NH+h_)*SEQ+s_))*HD + d_];
        ybuf[c] = v;
        sum += v; sq += v*v;
    }
    #pragma unroll
    for (int o = 16; o; o >>= 1){
        sum += __shfl_down_sync(0xffffffffu, sum, o);
        sq  += __shfl_down_sync(0xffffffffu, sq , o);
    }
    int wid = tid >> 5, lane = tid & 31;
    if (lane == 0){ rs[wid] = sum; rq[wid] = sq; }
    __syncthreads();
    if (tid < 32){
        sum = (tid < 8) ? rs[tid] : 0.0f;
        sq  = (tid < 8) ? rq[tid] : 0.0f;
        #pragma unroll
        for (int o = 4; o; o >>= 1){
            sum += __shfl_down_sync(0xffffffffu, sum, o);
            sq  += __shfl_down_sync(0xffffffffu, sq , o);
        }
        if (tid == 0){
            float mu  = sum * (1.0f/DM);
            float var = sq  * (1.0f/DM) - mu*mu;
            s_mu = mu;
            s_inv = rsqrtf(var + 1e-5f);
        }
    }
    __syncthreads();
    float mu = s_mu, inv = s_inv;
    for (int c = tid; c < DM; c += 256)
        out[(size_t)row*DM + c] = (ybuf[c] - mu)*inv*gamma[c] + beta[c];
}

// ============================================================
extern "C" void kernel_launch(void* const* d_in, const int* in_sizes, int n_in,
                              void* d_out, int out_size)
{
    const float*         x     = (const float*)d_in[0];
    const unsigned char* am    = (const unsigned char*)d_in[1];
    const float*         Wq    = (const float*)d_in[2];
    const float*         bq    = (const float*)d_in[3];
    const float*         Wk    = (const float*)d_in[4];
    const float*         bk    = (const float*)d_in[5];
    const float*         Wv    = (const float*)d_in[6];
    const float*         bv    = (const float*)d_in[7];
    const float*         gamma = (const float*)d_in[8];
    const float*         beta  = (const float*)d_in[9];
    float*               out   = (float*)d_out;
    (void)in_sizes; (void)n_in; (void)out_size;

    const int SM_QKV = 2*128*72*2*2;                    // 73728
    const int SM_SC  = 2*128*72*2*2 + 2*256*4;          // 75776
    const int SM_AV  = (2*128*64 + 2*64*200 + 128*72)*2;// 102400

    cudaFuncSetAttribute(k_qkv,    cudaFuncAttributeMaxDynamicSharedMemorySize, SM_QKV);
    cudaFuncSetAttribute(k_scores, cudaFuncAttributeMaxDynamicSharedMemorySize, SM_SC);
    cudaFuncSetAttribute(k_av,     cudaFuncAttributeMaxDynamicSharedMemorySize, SM_AV);

    k_cvt_x<<<BATCH*SEQ*DM/1024, 256>>>(x);
    k_cvt_w<<<dim3(DM*DM/1024, 3), 256>>>(Wq, Wk, Wv);

    k_qkv<<<dim3(3*DM/128, BATCH*SEQ/128), 256, SM_QKV>>>(bq, bk, bv);

    const int NT = (SEQ/128)*(SEQ/128 + 1)/2;   // 136 lower-tri tiles
    k_scores<<<dim3(NT, BHT), 256, SM_SC>>>(am);

    k_red<<<BHT*SEQ/256, 256>>>();

    k_av<<<dim3(SEQ/128, BHT), 256, SM_AV>>>();

    k_ln<<<BATCH*SEQ, 256>>>(x, gamma, beta, out);
}

// round 5
// speedup vs baseline: 7.2836x; 1.1548x over previous
#include <cuda_runtime.h>
#include <cuda_fp16.h>
#include <math.h>

#define SEQ    2048
#define DM     768
#define NH     4
#define HD     192
#define BATCH  4
#define BHT    16
#define NEGH   (-60000.0f)

// ---- device scratch ----
__device__ __align__(16) __half g_Xh [BATCH*SEQ*DM];
__device__ __align__(16) __half g_Wh [3*DM*DM];
__device__ __align__(16) __half g_Qh [BHT*SEQ*HD];
__device__ __align__(16) __half g_Kh [BHT*SEQ*HD];
__device__ __align__(16) __half g_Vh [BHT*SEQ*HD];
__device__ __align__(16) __half g_Sch[(size_t)BHT*SEQ*SEQ];
__device__ float  g_pl [BHT*16*SEQ];    // per-(bh,qt,k) partial sum of exp(s)
__device__ float  g_lse[BHT*SEQ];       // log sum exp per column
__device__ __align__(16) __half g_X1h[BHT*SEQ*HD];

// ---------------- helpers ----------------
__device__ __forceinline__ unsigned sptr(const void* p){
    return (unsigned)__cvta_generic_to_shared(p);
}
__device__ __forceinline__ void cpa16(unsigned dst, const void* src){
    asm volatile("cp.async.cg.shared.global [%0], [%1], 16;\n" :: "r"(dst), "l"(src));
}
__device__ __forceinline__ void cpa_commit(){ asm volatile("cp.async.commit_group;\n"); }
__device__ __forceinline__ void cpa_wait_all(){ asm volatile("cp.async.wait_group 0;\n"); }

__device__ __forceinline__ void ldsm4(unsigned r[4], unsigned a){
    asm volatile("ldmatrix.sync.aligned.m8n8.x4.shared.b16 {%0,%1,%2,%3},[%4];\n"
        : "=r"(r[0]),"=r"(r[1]),"=r"(r[2]),"=r"(r[3]) : "r"(a));
}
__device__ __forceinline__ void ldsm4t(unsigned r[4], unsigned a){
    asm volatile("ldmatrix.sync.aligned.m8n8.x4.trans.shared.b16 {%0,%1,%2,%3},[%4];\n"
        : "=r"(r[0]),"=r"(r[1]),"=r"(r[2]),"=r"(r[3]) : "r"(a));
}
__device__ __forceinline__ void mma16816(float* c, const unsigned* a, unsigned b0, unsigned b1){
    asm volatile("mma.sync.aligned.m16n8k16.row.col.f32.f16.f16.f32 "
        "{%0,%1,%2,%3},{%4,%5,%6,%7},{%8,%9},{%0,%1,%2,%3};\n"
        : "+f"(c[0]),"+f"(c[1]),"+f"(c[2]),"+f"(c[3])
        : "r"(a[0]),"r"(a[1]),"r"(a[2]),"r"(a[3]),"r"(b0),"r"(b1));
}

// ---------------- conversions ----------------
__global__ __launch_bounds__(256) void k_cvt_x(const float* __restrict__ x){
    int i = (blockIdx.x*256 + threadIdx.x)*4;
    float4 v = *(const float4*)(x+i);
    *(__half2*)&g_Xh[i]   = __floats2half2_rn(v.x,v.y);
    *(__half2*)&g_Xh[i+2] = __floats2half2_rn(v.z,v.w);
}
__global__ __launch_bounds__(256) void k_cvt_w(
    const float* __restrict__ Wq, const float* __restrict__ Wk, const float* __restrict__ Wv){
    int w = blockIdx.y;
    const float* src = (w==0)?Wq:((w==1)?Wk:Wv);
    __half* dst = g_Wh + w*DM*DM;
    int i = (blockIdx.x*256 + threadIdx.x)*4;
    float4 v = *(const float4*)(src+i);
    *(__half2*)&dst[i]   = __floats2half2_rn(v.x,v.y);
    *(__half2*)&dst[i+2] = __floats2half2_rn(v.z,v.w);
}

// ============================================================
// K1: QKV projection GEMM-NT, cp.async double-buffered
// ============================================================
__global__ __launch_bounds__(256,2) void k_qkv(
    const float* __restrict__ bq, const float* __restrict__ bk, const float* __restrict__ bv)
{
    extern __shared__ __align__(16) char smraw[];
    __half* As = (__half*)smraw;            // [2][128][72]
    __half* Bs = As + 2*128*72;             // [2][128][72]

    const int n0 = blockIdx.x*128, m0 = blockIdx.y*128;
    const int tid = threadIdx.x, lane = tid&31, wid = tid>>5;
    const int wm = wid>>2, wn = wid&3;
    const int lrow = lane&15, lcol = (lane>>4)*8;

    float acc[4][4][4] = {};
    const int ldr = tid>>3, ldc = (tid&7)*8;

    #pragma unroll
    for (int i=0;i<4;i++){
        int row = ldr + 32*i;
        cpa16(sptr(&As[(size_t)row*72 + ldc]), &g_Xh[(size_t)(m0+row)*DM + ldc]);
        cpa16(sptr(&Bs[(size_t)row*72 + ldc]), &g_Wh[(size_t)(n0+row)*DM + ldc]);
    }
    cpa_commit();

    const int NIT = DM/64;
    for (int it=0; it<NIT; it++){
        int cur = it & 1;
        cpa_wait_all();
        __syncthreads();
        if (it+1 < NIT){
            int nb = (it+1)&1, kb = (it+1)*64;
            #pragma unroll
            for (int i=0;i<4;i++){
                int row = ldr + 32*i;
                cpa16(sptr(&As[(size_t)(nb*128+row)*72 + ldc]), &g_Xh[(size_t)(m0+row)*DM + kb + ldc]);
                cpa16(sptr(&Bs[(size_t)(nb*128+row)*72 + ldc]), &g_Wh[(size_t)(n0+row)*DM + kb + ldc]);
            }
            cpa_commit();
        }
        const __half* Ab = As + (size_t)cur*128*72;
        const __half* Bb = Bs + (size_t)cur*128*72;
        #pragma unroll
        for (int kk=0;kk<4;kk++){
            unsigned a[4][4], b[2][4];
            #pragma unroll
            for (int mi=0;mi<4;mi++)
                ldsm4(a[mi], sptr(&Ab[(size_t)(wm*64+mi*16+lrow)*72 + kk*16+lcol]));
            #pragma unroll
            for (int np=0;np<2;np++)
                ldsm4(b[np], sptr(&Bb[(size_t)(wn*32+np*16+lrow)*72 + kk*16+lcol]));
            #pragma unroll
            for (int mi=0;mi<4;mi++)
                #pragma unroll
                for (int ni=0;ni<4;ni++)
                    mma16816(acc[mi][ni], a[mi], b[ni>>1][ni&1], b[ni>>1][(ni&1)+2]);
        }
        __syncthreads();
    }

    const int w = n0/DM;
    const float* bias = (w==0)?bq:((w==1)?bk:bv);
    __half* Out = (w==0)?g_Qh:((w==1)?g_Kh:g_Vh);

    #pragma unroll
    for (int mi=0;mi<4;mi++){
        int r0 = m0 + wm*64 + mi*16 + (lane>>2);
        #pragma unroll
        for (int ni=0;ni<4;ni++){
            int n = n0 + wn*32 + ni*8 + (lane&3)*2;
            int c = n - w*DM;
            int h = c/HD, d = c - h*HD;
            float b0f = bias[c], b1f = bias[c+1];
            #pragma unroll
            for (int p=0;p<2;p++){
                int m = r0 + p*8;
                int b_ = m>>11, s_ = m&(SEQ-1);
                __half2 hv = __floats2half2_rn(acc[mi][ni][2*p]+b0f, acc[mi][ni][2*p+1]+b1f);
                *(__half2*)&Out[((size_t)((b_*NH+h)*SEQ+s_))*HD + d] = hv;
            }
        }
    }
}

// ============================================================
// K2: scores + fused per-tile column sum-of-exp (LSE form, no max)
// ============================================================
__global__ __launch_bounds__(256,2) void k_scores(const unsigned char* __restrict__ am)
{
    extern __shared__ __align__(16) char smraw[];
    __half* As = (__half*)smraw;            // [2][128][72]
    __half* Bs = As + 2*128*72;
    float*  pl = (float*)(Bs + 2*128*72);   // [2][128]

    const int bh = blockIdx.y, b_ = bh>>2;
    int t = blockIdx.x;
    int qt = (int)((sqrtf(8.f*(float)t+1.f)-1.f)*0.5f);
    while ((qt+1)*(qt+2)/2 <= t) ++qt;
    while (qt*(qt+1)/2 > t)      --qt;
    int kt = t - qt*(qt+1)/2;
    const int q0 = qt*128, k0 = kt*128;
    const bool diag = (kt == qt);

    const __half* Qp = g_Qh + (size_t)bh*SEQ*HD;
    const __half* Kp = g_Kh + (size_t)bh*SEQ*HD;
    __half* Sp = g_Sch + (size_t)bh*SEQ*SEQ;

    const int tid = threadIdx.x, lane = tid&31, wid = tid>>5;
    const int wm = wid>>2, wn = wid&3;
    const int lrow = lane&15, lcol = (lane>>4)*8;
    const int ldr = tid>>3, ldc = (tid&7)*8;

    float acc[4][4][4] = {};

    #pragma unroll
    for (int i=0;i<4;i++){
        int row = ldr + 32*i;
        cpa16(sptr(&As[(size_t)row*72 + ldc]), &Qp[(size_t)(q0+row)*HD + ldc]);
        cpa16(sptr(&Bs[(size_t)row*72 + ldc]), &Kp[(size_t)(k0+row)*HD + ldc]);
    }
    cpa_commit();

    const int NIT = HD/64;
    for (int it=0; it<NIT; it++){
        int cur = it & 1;
        cpa_wait_all();
        __syncthreads();
        if (it+1 < NIT){
            int nb = (it+1)&1, kb = (it+1)*64;
            #pragma unroll
            for (int i=0;i<4;i++){
                int row = ldr + 32*i;
                cpa16(sptr(&As[(size_t)(nb*128+row)*72 + ldc]), &Qp[(size_t)(q0+row)*HD + kb + ldc]);
                cpa16(sptr(&Bs[(size_t)(nb*128+row)*72 + ldc]), &Kp[(size_t)(k0+row)*HD + kb + ldc]);
            }
            cpa_commit();
        }
        const __half* Ab = As + (size_t)cur*128*72;
        const __half* Bb = Bs + (size_t)cur*128*72;
        #pragma unroll
        for (int kk=0;kk<4;kk++){
            unsigned a[4][4], b[2][4];
            #pragma unroll
            for (int mi=0;mi<4;mi++)
                ldsm4(a[mi], sptr(&Ab[(size_t)(wm*64+mi*16+lrow)*72 + kk*16+lcol]));
            #pragma unroll
            for (int np=0;np<2;np++)
                ldsm4(b[np], sptr(&Bb[(size_t)(wn*32+np*16+lrow)*72 + kk*16+lcol]));
            #pragma unroll
            for (int mi=0;mi<4;mi++)
                #pragma unroll
                for (int ni=0;ni<4;ni++)
                    mma16816(acc[mi][ni], a[mi], b[ni>>1][ni&1], b[ni>>1][(ni&1)+2]);
        }
        __syncthreads();
    }

    // ---- epilogue: store masked fp16 scores + column sum of exp ----
    float coll[4][2];
    #pragma unroll
    for (int ni=0;ni<4;ni++){ coll[ni][0]=coll[ni][1]=0.f; }

    #pragma unroll
    for (int mi=0;mi<4;mi++){
        int r0 = q0 + wm*64 + mi*16 + (lane>>2);
        #pragma unroll
        for (int p=0;p<2;p++){
            int q = r0 + p*8;
            bool pad = am[b_*SEQ + q] != 0;
            #pragma unroll
            for (int ni=0;ni<4;ni++){
                int k = k0 + wn*32 + ni*8 + (lane&3)*2;
                float v0, v1;
                if (diag){
                    v0 = (k   > q || pad) ? NEGH : acc[mi][ni][2*p]  *0.05f;
                    v1 = (k+1 > q || pad) ? NEGH : acc[mi][ni][2*p+1]*0.05f;
                } else {
                    v0 = pad ? NEGH : acc[mi][ni][2*p]  *0.05f;
                    v1 = pad ? NEGH : acc[mi][ni][2*p+1]*0.05f;
                }
                __half2 h2 = __floats2half2_rn(v0,v1);
                *(__half2*)&Sp[(size_t)q*SEQ + k] = h2;
                float2 f = __half22float2(h2);
                coll[ni][0] += __expf(f.x);     // exp(-60000) underflows to 0
                coll[ni][1] += __expf(f.y);
            }
        }
    }
    // reduce across the 8 row-groups of the warp (xor 4/8/16 keeps lane&3)
    #pragma unroll
    for (int off=4; off<32; off<<=1){
        #pragma unroll
        for (int ni=0;ni<4;ni++){
            coll[ni][0] += __shfl_xor_sync(0xffffffffu, coll[ni][0], off);
            coll[ni][1] += __shfl_xor_sync(0xffffffffu, coll[ni][1], off);
        }
    }
    if (lane < 4){
        #pragma unroll
        for (int ni=0;ni<4;ni++){
            int col = wn*32 + ni*8 + lane*2;
            pl[wm*128 + col]     = coll[ni][0];
            pl[wm*128 + col + 1] = coll[ni][1];
        }
    }
    __syncthreads();
    if (tid < 128){
        size_t o = ((size_t)(bh*16 + qt))*SEQ + k0 + tid;
        g_pl[o] = pl[tid] + pl[128+tid];
    }
}

// ============================================================
// K3: reduce column partial sums over qt -> lse
// ============================================================
__global__ __launch_bounds__(256) void k_red()
{
    int idx = blockIdx.x*256 + threadIdx.x;     // over BHT*SEQ
    int bh = idx >> 11;
    int k  = idx & (SEQ-1);
    int kt = k >> 7;
    float l = 0.f;
    for (int qt = kt; qt < 16; qt++)
        l += g_pl[((size_t)(bh*16 + qt))*SEQ + k];
    g_lse[idx] = __logf(l);
}

// ============================================================
// K4: X1 = P@V, P = exp(s - lse) built on the fly
// ============================================================
__global__ __launch_bounds__(256,2) void k_av()
{
    extern __shared__ __align__(16) char smraw[];
    __half* Ss = (__half*)smraw;            // [2][128][64]
    __half* Vs = Ss + 2*128*64;             // [2][64][200]
    __half* Ps = Vs + 2*64*200;             // [128][72]

    const int qt = (SEQ/128 - 1) - blockIdx.x;
    const int bh = blockIdx.y;
    const int q0 = qt*128;
    const int kmax = (qt+1)*128;

    const __half* Vp = g_Vh + (size_t)bh*SEQ*HD;
    const __half* Sp = g_Sch + (size_t)bh*SEQ*SEQ;
    const float* lse = g_lse + bh*SEQ;

    const int tid = threadIdx.x, lane = tid&31, wid = tid>>5;
    const int wm = wid>>2, wn = wid&3;
    const int lrow = lane&15, lcol = (lane>>4)*8;

    float acc[4][6][4] = {};
    const int srow = tid>>3, svc = (tid&7)*8;

    {
        #pragma unroll
        for (int i=0;i<4;i++){
            int row = srow + 32*i;
            cpa16(sptr(&Ss[(size_t)row*64 + svc]), &Sp[(size_t)(q0+row)*SEQ + svc]);
        }
        #pragma unroll
        for (int i=0;i<6;i++){
            int idx = tid + 256*i;
            int row = idx/24, vc = (idx%24)*8;
            cpa16(sptr(&Vs[(size_t)row*200 + vc]), &Vp[(size_t)row*HD + vc]);
        }
        cpa_commit();
    }

    const int NIT = kmax >> 6;
    for (int it=0; it<NIT; it++){
        int cur = it & 1;
        cpa_wait_all();
        __syncthreads();
        if (it+1 < NIT){
            int nb = (it+1)&1, kb = (it+1)*64;
            #pragma unroll
            for (int i=0;i<4;i++){
                int row = srow + 32*i;
                cpa16(sptr(&Ss[(size_t)(nb*128+row)*64 + svc]), &Sp[(size_t)(q0+row)*SEQ + kb + svc]);
            }
            #pragma unroll
            for (int i=0;i<6;i++){
                int idx = tid + 256*i;
                int row = idx/24, vc = (idx%24)*8;
                cpa16(sptr(&Vs[(size_t)(nb*64+row)*200 + vc]), &Vp[(size_t)(kb+row)*HD + vc]);
            }
            cpa_commit();
        }
        // transform: Ss[cur] -> Ps, P = exp(s - lse)
        const __half* Sb = Ss + (size_t)cur*128*64;
        int kbase = it*64;
        #pragma unroll
        for (int i=0;i<4;i++){
            int row = srow + 32*i;
            uint4 raw = *(const uint4*)&Sb[(size_t)row*64 + svc];
            __half2* hp = (__half2*)&raw;
            __half2 o[4];
            #pragma unroll
            for (int j=0;j<4;j++){
                float2 f = __half22float2(hp[j]);
                int k2 = kbase + svc + j*2;
                float e0 = __expf(f.x - __ldg(&lse[k2]));
                float e1 = __expf(f.y - __ldg(&lse[k2+1]));
                o[j] = __floats2half2_rn(e0,e1);
            }
            *(uint4*)&Ps[(size_t)row*72 + svc] = *(uint4*)o;
        }
        __syncthreads();
        const __half* Vb = Vs + (size_t)cur*64*200;
        #pragma unroll
        for (int kk=0;kk<4;kk++){
            unsigned a[4][4], b[3][4];
            #pragma unroll
            for (int mi=0;mi<4;mi++)
                ldsm4(a[mi], sptr(&Ps[(size_t)(wm*64+mi*16+lrow)*72 + kk*16+lcol]));
            #pragma unroll
            for (int np=0;np<3;np++)
                ldsm4t(b[np], sptr(&Vb[(size_t)(kk*16+lrow)*200 + wn*48+np*16+lcol]));
            #pragma unroll
            for (int mi=0;mi<4;mi++)
                #pragma unroll
                for (int ni=0;ni<6;ni++)
                    mma16816(acc[mi][ni], a[mi], b[ni>>1][(ni&1)*2], b[ni>>1][(ni&1)*2+1]);
        }
    }

    #pragma unroll
    for (int mi=0;mi<4;mi++){
        int r0 = q0 + wm*64 + mi*16 + (lane>>2);
        #pragma unroll
        for (int ni=0;ni<6;ni++){
            int d = wn*48 + ni*8 + (lane&3)*2;
            #pragma unroll
            for (int p=0;p<2;p++){
                int q = r0 + p*8;
                *(__half2*)&g_X1h[((size_t)(bh*SEQ+q))*HD + d] =
                    __floats2half2_rn(acc[mi][ni][2*p], acc[mi][ni][2*p+1]);
            }
        }
    }
}

// ============================================================
// K5: y = x + X1, LayerNorm
// ============================================================
__global__ __launch_bounds__(256) void k_ln(
    const float* __restrict__ x,
    const float* __restrict__ gamma,
    const float* __restrict__ beta,
    float* __restrict__ out)
{
    int row = blockIdx.x;
    int b_ = row >> 11, s_ = row & (SEQ-1);
    int tid = threadIdx.x;

    __shared__ float ybuf[DM];
    __shared__ float rs[32], rq[32];
    __shared__ float s_mu, s_inv;

    float sum = 0.0f, sq = 0.0f;
    for (int c = tid; c < DM; c += 256){
        int h_ = c/HD, d_ = c - h_*HD;
        float v = x[(size_t)row*DM + c]
                + __half2float(g_X1h[((size_t)((b_*NH+h_)*SEQ+s_))*HD + d_]);
        ybuf[c] = v;
        sum += v; sq += v*v;
    }
    #pragma unroll
    for (int o = 16; o; o >>= 1){
        sum += __shfl_down_sync(0xffffffffu, sum, o);
        sq  += __shfl_down_sync(0xffffffffu, sq , o);
    }
    int wid = tid >> 5, lane = tid & 31;
    if (lane == 0){ rs[wid] = sum; rq[wid] = sq; }
    __syncthreads();
    if (tid < 32){
        sum = (tid < 8) ? rs[tid] : 0.0f;
        sq  = (tid < 8) ? rq[tid] : 0.0f;
        #pragma unroll
        for (int o = 4; o; o >>= 1){
            sum += __shfl_down_sync(0xffffffffu, sum, o);
            sq  += __shfl_down_sync(0xffffffffu, sq , o);
        }
        if (tid == 0){
            float mu  = sum * (1.0f/DM);
            float var = sq  * (1.0f/DM) - mu*mu;
            s_mu = mu;
            s_inv = rsqrtf(var + 1e-5f);
        }
    }
    __syncthreads();
    float mu = s_mu, inv = s_inv;
    for (int c = tid; c < DM; c += 256)
        out[(size_t)row*DM + c] = (ybuf[c] - mu)*inv*gamma[c] + beta[c];
}

// ============================================================
extern "C" void kernel_launch(void* const* d_in, const int* in_sizes, int n_in,
                              void* d_out, int out_size)
{
    const float*         x     = (const float*)d_in[0];
    const unsigned char* am    = (const unsigned char*)d_in[1];
    const float*         Wq    = (const float*)d_in[2];
    const float*         bq    = (const float*)d_in[3];
    const float*         Wk    = (const float*)d_in[4];
    const float*         bk    = (const float*)d_in[5];
    const float*         Wv    = (const float*)d_in[6];
    const float*         bv    = (const float*)d_in[7];
    const float*         gamma = (const float*)d_in[8];
    const float*         beta  = (const float*)d_in[9];
    float*               out   = (float*)d_out;
    (void)in_sizes; (void)n_in; (void)out_size;

    const int SM_QKV = 2*128*72*2*2;                    // 73728
    const int SM_SC  = 2*128*72*2*2 + 2*128*4;          // 74752
    const int SM_AV  = (2*128*64 + 2*64*200 + 128*72)*2;// 102400

    cudaFuncSetAttribute(k_qkv,    cudaFuncAttributeMaxDynamicSharedMemorySize, SM_QKV);
    cudaFuncSetAttribute(k_scores, cudaFuncAttributeMaxDynamicSharedMemorySize, SM_SC);
    cudaFuncSetAttribute(k_av,     cudaFuncAttributeMaxDynamicSharedMemorySize, SM_AV);

    k_cvt_x<<<BATCH*SEQ*DM/1024, 256>>>(x);
    k_cvt_w<<<dim3(DM*DM/1024, 3), 256>>>(Wq, Wk, Wv);

    k_qkv<<<dim3(3*DM/128, BATCH*SEQ/128), 256, SM_QKV>>>(bq, bk, bv);

    const int NT = (SEQ/128)*(SEQ/128 + 1)/2;   // 136 lower-tri tiles
    k_scores<<<dim3(NT, BHT), 256, SM_SC>>>(am);

    k_red<<<BHT*SEQ/256, 256>>>();

    k_av<<<dim3(SEQ/128, BHT), 256, SM_AV>>>();

    k_ln<<<BATCH*SEQ, 256>>>(x, gamma, beta, out);
}

// round 6
// speedup vs baseline: 8.2559x; 1.1335x over previous
#include <cuda_runtime.h>
#include <cuda_fp16.h>
#include <math.h>

#define SEQ    2048
#define DM     768
#define NH     4
#define HD     192
#define BATCH  4
#define BHT    16
#define NEGH   (-60000.0f)

// ---- device scratch ----
__device__ __align__(16) __half g_Xh [BATCH*SEQ*DM];
__device__ __align__(16) __half g_Wh [3*DM*DM];
__device__ __align__(16) __half g_Qh [BHT*SEQ*HD];
__device__ __align__(16) __half g_Kh [BHT*SEQ*HD];
__device__ __align__(16) __half g_Vh [BHT*SEQ*HD];
__device__ __align__(16) __half g_Sch[(size_t)BHT*SEQ*SEQ];
__device__ float  g_pl [BHT*16*SEQ];    // per-(bh,qt,k) partial sum of exp(s)
__device__ float  g_lse[BHT*SEQ];       // log sum exp per column
__device__ __align__(16) __half g_X1p[4*BHT*SEQ*HD];   // split-K partials (4 slots)

// ---------------- helpers ----------------
__device__ __forceinline__ unsigned sptr(const void* p){
    return (unsigned)__cvta_generic_to_shared(p);
}
__device__ __forceinline__ void cpa16(unsigned dst, const void* src){
    asm volatile("cp.async.cg.shared.global [%0], [%1], 16;\n" :: "r"(dst), "l"(src));
}
__device__ __forceinline__ void cpa_commit(){ asm volatile("cp.async.commit_group;\n"); }
__device__ __forceinline__ void cpa_wait_all(){ asm volatile("cp.async.wait_group 0;\n"); }

__device__ __forceinline__ void ldsm4(unsigned r[4], unsigned a){
    asm volatile("ldmatrix.sync.aligned.m8n8.x4.shared.b16 {%0,%1,%2,%3},[%4];\n"
        : "=r"(r[0]),"=r"(r[1]),"=r"(r[2]),"=r"(r[3]) : "r"(a));
}
__device__ __forceinline__ void ldsm4t(unsigned r[4], unsigned a){
    asm volatile("ldmatrix.sync.aligned.m8n8.x4.trans.shared.b16 {%0,%1,%2,%3},[%4];\n"
        : "=r"(r[0]),"=r"(r[1]),"=r"(r[2]),"=r"(r[3]) : "r"(a));
}
__device__ __forceinline__ void mma16816(float* c, const unsigned* a, unsigned b0, unsigned b1){
    asm volatile("mma.sync.aligned.m16n8k16.row.col.f32.f16.f16.f32 "
        "{%0,%1,%2,%3},{%4,%5,%6,%7},{%8,%9},{%0,%1,%2,%3};\n"
        : "+f"(c[0]),"+f"(c[1]),"+f"(c[2]),"+f"(c[3])
        : "r"(a[0]),"r"(a[1]),"r"(a[2]),"r"(a[3]),"r"(b0),"r"(b1));
}

// ---------------- conversions ----------------
__global__ __launch_bounds__(256) void k_cvt_x(const float* __restrict__ x){
    int i = (blockIdx.x*256 + threadIdx.x)*4;
    float4 v = *(const float4*)(x+i);
    *(__half2*)&g_Xh[i]   = __floats2half2_rn(v.x,v.y);
    *(__half2*)&g_Xh[i+2] = __floats2half2_rn(v.z,v.w);
}
__global__ __launch_bounds__(256) void k_cvt_w(
    const float* __restrict__ Wq, const float* __restrict__ Wk, const float* __restrict__ Wv){
    int w = blockIdx.y;
    const float* src = (w==0)?Wq:((w==1)?Wk:Wv);
    __half* dst = g_Wh + w*DM*DM;
    int i = (blockIdx.x*256 + threadIdx.x)*4;
    float4 v = *(const float4*)(src+i);
    *(__half2*)&dst[i]   = __floats2half2_rn(v.x,v.y);
    *(__half2*)&dst[i+2] = __floats2half2_rn(v.z,v.w);
}

// ============================================================
// K1: QKV projection GEMM-NT, cp.async double-buffered
// ============================================================
__global__ __launch_bounds__(256,2) void k_qkv(
    const float* __restrict__ bq, const float* __restrict__ bk, const float* __restrict__ bv)
{
    extern __shared__ __align__(16) char smraw[];
    __half* As = (__half*)smraw;            // [2][128][72]
    __half* Bs = As + 2*128*72;             // [2][128][72]

    const int n0 = blockIdx.x*128, m0 = blockIdx.y*128;
    const int tid = threadIdx.x, lane = tid&31, wid = tid>>5;
    const int wm = wid>>2, wn = wid&3;
    const int lrow = lane&15, lcol = (lane>>4)*8;

    float acc[4][4][4] = {};
    const int ldr = tid>>3, ldc = (tid&7)*8;

    #pragma unroll
    for (int i=0;i<4;i++){
        int row = ldr + 32*i;
        cpa16(sptr(&As[(size_t)row*72 + ldc]), &g_Xh[(size_t)(m0+row)*DM + ldc]);
        cpa16(sptr(&Bs[(size_t)row*72 + ldc]), &g_Wh[(size_t)(n0+row)*DM + ldc]);
    }
    cpa_commit();

    const int NIT = DM/64;
    for (int it=0; it<NIT; it++){
        int cur = it & 1;
        cpa_wait_all();
        __syncthreads();
        if (it+1 < NIT){
            int nb = (it+1)&1, kb = (it+1)*64;
            #pragma unroll
            for (int i=0;i<4;i++){
                int row = ldr + 32*i;
                cpa16(sptr(&As[(size_t)(nb*128+row)*72 + ldc]), &g_Xh[(size_t)(m0+row)*DM + kb + ldc]);
                cpa16(sptr(&Bs[(size_t)(nb*128+row)*72 + ldc]), &g_Wh[(size_t)(n0+row)*DM + kb + ldc]);
            }
            cpa_commit();
        }
        const __half* Ab = As + (size_t)cur*128*72;
        const __half* Bb = Bs + (size_t)cur*128*72;
        #pragma unroll
        for (int kk=0;kk<4;kk++){
            unsigned a[4][4], b[2][4];
            #pragma unroll
            for (int mi=0;mi<4;mi++)
                ldsm4(a[mi], sptr(&Ab[(size_t)(wm*64+mi*16+lrow)*72 + kk*16+lcol]));
            #pragma unroll
            for (int np=0;np<2;np++)
                ldsm4(b[np], sptr(&Bb[(size_t)(wn*32+np*16+lrow)*72 + kk*16+lcol]));
            #pragma unroll
            for (int mi=0;mi<4;mi++)
                #pragma unroll
                for (int ni=0;ni<4;ni++)
                    mma16816(acc[mi][ni], a[mi], b[ni>>1][ni&1], b[ni>>1][(ni&1)+2]);
        }
        __syncthreads();
    }

    const int w = n0/DM;
    const float* bias = (w==0)?bq:((w==1)?bk:bv);
    __half* Out = (w==0)?g_Qh:((w==1)?g_Kh:g_Vh);

    #pragma unroll
    for (int mi=0;mi<4;mi++){
        int r0 = m0 + wm*64 + mi*16 + (lane>>2);
        #pragma unroll
        for (int ni=0;ni<4;ni++){
            int n = n0 + wn*32 + ni*8 + (lane&3)*2;
            int c = n - w*DM;
            int h = c/HD, d = c - h*HD;
            float b0f = bias[c], b1f = bias[c+1];
            #pragma unroll
            for (int p=0;p<2;p++){
                int m = r0 + p*8;
                int b_ = m>>11, s_ = m&(SEQ-1);
                __half2 hv = __floats2half2_rn(acc[mi][ni][2*p]+b0f, acc[mi][ni][2*p+1]+b1f);
                *(__half2*)&Out[((size_t)((b_*NH+h)*SEQ+s_))*HD + d] = hv;
            }
        }
    }
}

// ============================================================
// K2: scores + fused per-tile column sum-of-exp (LSE form)
// ============================================================
__global__ __launch_bounds__(256,2) void k_scores(const unsigned char* __restrict__ am)
{
    extern __shared__ __align__(16) char smraw[];
    __half* As = (__half*)smraw;            // [2][128][72]
    __half* Bs = As + 2*128*72;
    float*  pl = (float*)(Bs + 2*128*72);   // [2][128]

    const int bh = blockIdx.y, b_ = bh>>2;
    int t = blockIdx.x;
    int qt = (int)((sqrtf(8.f*(float)t+1.f)-1.f)*0.5f);
    while ((qt+1)*(qt+2)/2 <= t) ++qt;
    while (qt*(qt+1)/2 > t)      --qt;
    int kt = t - qt*(qt+1)/2;
    const int q0 = qt*128, k0 = kt*128;
    const bool diag = (kt == qt);

    const __half* Qp = g_Qh + (size_t)bh*SEQ*HD;
    const __half* Kp = g_Kh + (size_t)bh*SEQ*HD;
    __half* Sp = g_Sch + (size_t)bh*SEQ*SEQ;

    const int tid = threadIdx.x, lane = tid&31, wid = tid>>5;
    const int wm = wid>>2, wn = wid&3;
    const int lrow = lane&15, lcol = (lane>>4)*8;
    const int ldr = tid>>3, ldc = (tid&7)*8;

    float acc[4][4][4] = {};

    #pragma unroll
    for (int i=0;i<4;i++){
        int row = ldr + 32*i;
        cpa16(sptr(&As[(size_t)row*72 + ldc]), &Qp[(size_t)(q0+row)*HD + ldc]);
        cpa16(sptr(&Bs[(size_t)row*72 + ldc]), &Kp[(size_t)(k0+row)*HD + ldc]);
    }
    cpa_commit();

    const int NIT = HD/64;
    for (int it=0; it<NIT; it++){
        int cur = it & 1;
        cpa_wait_all();
        __syncthreads();
        if (it+1 < NIT){
            int nb = (it+1)&1, kb = (it+1)*64;
            #pragma unroll
            for (int i=0;i<4;i++){
                int row = ldr + 32*i;
                cpa16(sptr(&As[(size_t)(nb*128+row)*72 + ldc]), &Qp[(size_t)(q0+row)*HD + kb + ldc]);
                cpa16(sptr(&Bs[(size_t)(nb*128+row)*72 + ldc]), &Kp[(size_t)(k0+row)*HD + kb + ldc]);
            }
            cpa_commit();
        }
        const __half* Ab = As + (size_t)cur*128*72;
        const __half* Bb = Bs + (size_t)cur*128*72;
        #pragma unroll
        for (int kk=0;kk<4;kk++){
            unsigned a[4][4], b[2][4];
            #pragma unroll
            for (int mi=0;mi<4;mi++)
                ldsm4(a[mi], sptr(&Ab[(size_t)(wm*64+mi*16+lrow)*72 + kk*16+lcol]));
            #pragma unroll
            for (int np=0;np<2;np++)
                ldsm4(b[np], sptr(&Bb[(size_t)(wn*32+np*16+lrow)*72 + kk*16+lcol]));
            #pragma unroll
            for (int mi=0;mi<4;mi++)
                #pragma unroll
                for (int ni=0;ni<4;ni++)
                    mma16816(acc[mi][ni], a[mi], b[ni>>1][ni&1], b[ni>>1][(ni&1)+2]);
        }
        __syncthreads();
    }

    float coll[4][2];
    #pragma unroll
    for (int ni=0;ni<4;ni++){ coll[ni][0]=coll[ni][1]=0.f; }

    #pragma unroll
    for (int mi=0;mi<4;mi++){
        int r0 = q0 + wm*64 + mi*16 + (lane>>2);
        #pragma unroll
        for (int p=0;p<2;p++){
            int q = r0 + p*8;
            bool pad = am[b_*SEQ + q] != 0;
            #pragma unroll
            for (int ni=0;ni<4;ni++){
                int k = k0 + wn*32 + ni*8 + (lane&3)*2;
                float v0, v1;
                if (diag){
                    v0 = (k   > q || pad) ? NEGH : acc[mi][ni][2*p]  *0.05f;
                    v1 = (k+1 > q || pad) ? NEGH : acc[mi][ni][2*p+1]*0.05f;
                } else {
                    v0 = pad ? NEGH : acc[mi][ni][2*p]  *0.05f;
                    v1 = pad ? NEGH : acc[mi][ni][2*p+1]*0.05f;
                }
                __half2 h2 = __floats2half2_rn(v0,v1);
                *(__half2*)&Sp[(size_t)q*SEQ + k] = h2;
                float2 f = __half22float2(h2);
                coll[ni][0] += __expf(f.x);
                coll[ni][1] += __expf(f.y);
            }
        }
    }
    #pragma unroll
    for (int off=4; off<32; off<<=1){
        #pragma unroll
        for (int ni=0;ni<4;ni++){
            coll[ni][0] += __shfl_xor_sync(0xffffffffu, coll[ni][0], off);
            coll[ni][1] += __shfl_xor_sync(0xffffffffu, coll[ni][1], off);
        }
    }
    if (lane < 4){
        #pragma unroll
        for (int ni=0;ni<4;ni++){
            int col = wn*32 + ni*8 + lane*2;
            pl[wm*128 + col]     = coll[ni][0];
            pl[wm*128 + col + 1] = coll[ni][1];
        }
    }
    __syncthreads();
    if (tid < 128){
        size_t o = ((size_t)(bh*16 + qt))*SEQ + k0 + tid;
        g_pl[o] = pl[tid] + pl[128+tid];
    }
}

// ============================================================
// K3: reduce column partial sums over qt -> lse
// ============================================================
__global__ __launch_bounds__(256) void k_red()
{
    int idx = blockIdx.x*256 + threadIdx.x;
    int bh = idx >> 11;
    int k  = idx & (SEQ-1);
    int kt = k >> 7;
    float l = 0.f;
    for (int qt = kt; qt < 16; qt++)
        l += g_pl[((size_t)(bh*16 + qt))*SEQ + k];
    g_lse[idx] = __logf(l);
}

// ============================================================
// K4: X1 partial = P@V over a k-split of 4 tiles (512 keys).
// grid: (40, BHT). block idx -> (qt, ks) via group arithmetic.
// ============================================================
__global__ __launch_bounds__(256,2) void k_av()
{
    extern __shared__ __align__(16) char smraw[];
    __half* Ss = (__half*)smraw;            // [2][128][64]
    __half* Vs = Ss + 2*128*64;             // [2][64][200]
    __half* Ps = Vs + 2*64*200;             // [128][72]

    // decode (qt, ks): groups g=qt/4 have g+1 splits each
    int idx = 39 - (int)blockIdx.x;         // big blocks first
    int g, base;
    if      (idx < 4)  { g=0; base=0;  }
    else if (idx < 12) { g=1; base=4;  }
    else if (idx < 24) { g=2; base=12; }
    else               { g=3; base=24; }
    int off = idx - base;
    const int qt = 4*g + off/(g+1);
    const int ks = off % (g+1);

    const int bh = blockIdx.y;
    const int q0 = qt*128;
    const int kstart = ks*512;
    const int kend   = min(kstart+512, (qt+1)*128);

    const __half* Vp = g_Vh + (size_t)bh*SEQ*HD;
    const __half* Sp = g_Sch + (size_t)bh*SEQ*SEQ;
    const float* lse = g_lse + bh*SEQ;

    const int tid = threadIdx.x, lane = tid&31, wid = tid>>5;
    const int wm = wid>>2, wn = wid&3;
    const int lrow = lane&15, lcol = (lane>>4)*8;

    float acc[4][6][4] = {};
    const int srow = tid>>3, svc = (tid&7)*8;

    {
        #pragma unroll
        for (int i=0;i<4;i++){
            int row = srow + 32*i;
            cpa16(sptr(&Ss[(size_t)row*64 + svc]), &Sp[(size_t)(q0+row)*SEQ + kstart + svc]);
        }
        #pragma unroll
        for (int i=0;i<6;i++){
            int ii = tid + 256*i;
            int row = ii/24, vc = (ii%24)*8;
            cpa16(sptr(&Vs[(size_t)row*200 + vc]), &Vp[(size_t)(kstart+row)*HD + vc]);
        }
        cpa_commit();
    }

    const int NIT = (kend - kstart) >> 6;
    for (int it=0; it<NIT; it++){
        int cur = it & 1;
        cpa_wait_all();
        __syncthreads();
        if (it+1 < NIT){
            int nb = (it+1)&1, kb = kstart + (it+1)*64;
            #pragma unroll
            for (int i=0;i<4;i++){
                int row = srow + 32*i;
                cpa16(sptr(&Ss[(size_t)(nb*128+row)*64 + svc]), &Sp[(size_t)(q0+row)*SEQ + kb + svc]);
            }
            #pragma unroll
            for (int i=0;i<6;i++){
                int ii = tid + 256*i;
                int row = ii/24, vc = (ii%24)*8;
                cpa16(sptr(&Vs[(size_t)(nb*64+row)*200 + vc]), &Vp[(size_t)(kb+row)*HD + vc]);
            }
            cpa_commit();
        }
        const __half* Sb = Ss + (size_t)cur*128*64;
        int kbase = kstart + it*64;
        #pragma unroll
        for (int i=0;i<4;i++){
            int row = srow + 32*i;
            uint4 raw = *(const uint4*)&Sb[(size_t)row*64 + svc];
            __half2* hp = (__half2*)&raw;
            __half2 o[4];
            #pragma unroll
            for (int j=0;j<4;j++){
                float2 f = __half22float2(hp[j]);
                int k2 = kbase + svc + j*2;
                float e0 = __expf(f.x - __ldg(&lse[k2]));
                float e1 = __expf(f.y - __ldg(&lse[k2+1]));
                o[j] = __floats2half2_rn(e0,e1);
            }
            *(uint4*)&Ps[(size_t)row*72 + svc] = *(uint4*)o;
        }
        __syncthreads();
        const __half* Vb = Vs + (size_t)cur*64*200;
        #pragma unroll
        for (int kk=0;kk<4;kk++){
            unsigned a[4][4], b[3][4];
            #pragma unroll
            for (int mi=0;mi<4;mi++)
                ldsm4(a[mi], sptr(&Ps[(size_t)(wm*64+mi*16+lrow)*72 + kk*16+lcol]));
            #pragma unroll
            for (int np=0;np<3;np++)
                ldsm4t(b[np], sptr(&Vb[(size_t)(kk*16+lrow)*200 + wn*48+np*16+lcol]));
            #pragma unroll
            for (int mi=0;mi<4;mi++)
                #pragma unroll
                for (int ni=0;ni<6;ni++)
                    mma16816(acc[mi][ni], a[mi], b[ni>>1][(ni&1)*2], b[ni>>1][(ni&1)*2+1]);
        }
    }

    __half* Xp = g_X1p + (size_t)ks*BHT*SEQ*HD;
    #pragma unroll
    for (int mi=0;mi<4;mi++){
        int r0 = q0 + wm*64 + mi*16 + (lane>>2);
        #pragma unroll
        for (int ni=0;ni<6;ni++){
            int d = wn*48 + ni*8 + (lane&3)*2;
            #pragma unroll
            for (int p=0;p<2;p++){
                int q = r0 + p*8;
                *(__half2*)&Xp[((size_t)(bh*SEQ+q))*HD + d] =
                    __floats2half2_rn(acc[mi][ni][2*p], acc[mi][ni][2*p+1]);
            }
        }
    }
}

// ============================================================
// K5: y = x + sum(X1 partials), LayerNorm
// ============================================================
__global__ __launch_bounds__(256) void k_ln(
    const float* __restrict__ x,
    const float* __restrict__ gamma,
    const float* __restrict__ beta,
    float* __restrict__ out)
{
    int row = blockIdx.x;
    int b_ = row >> 11, s_ = row & (SEQ-1);
    int tid = threadIdx.x;
    int ns = (s_ >> 9) + 1;         // (qt/4)+1 = s_/512 + 1

    __shared__ float ybuf[DM];
    __shared__ float rs[32], rq[32];
    __shared__ float s_mu, s_inv;

    float sum = 0.0f, sq = 0.0f;
    for (int c = tid; c < DM; c += 256){
        int h_ = c/HD, d_ = c - h_*HD;
        size_t o = ((size_t)((b_*NH+h_)*SEQ+s_))*HD + d_;
        float v = x[(size_t)row*DM + c];
        for (int s = 0; s < ns; s++)
            v += __half2float(__ldg(&g_X1p[(size_t)s*BHT*SEQ*HD + o]));
        ybuf[c] = v;
        sum += v; sq += v*v;
    }
    #pragma unroll
    for (int o = 16; o; o >>= 1){
        sum += __shfl_down_sync(0xffffffffu, sum, o);
        sq  += __shfl_down_sync(0xffffffffu, sq , o);
    }
    int wid = tid >> 5, lane = tid & 31;
    if (lane == 0){ rs[wid] = sum; rq[wid] = sq; }
    __syncthreads();
    if (tid < 32){
        sum = (tid < 8) ? rs[tid] : 0.0f;
        sq  = (tid < 8) ? rq[tid] : 0.0f;
        #pragma unroll
        for (int o = 4; o; o >>= 1){
            sum += __shfl_down_sync(0xffffffffu, sum, o);
            sq  += __shfl_down_sync(0xffffffffu, sq , o);
        }
        if (tid == 0){
            float mu  = sum * (1.0f/DM);
            float var = sq  * (1.0f/DM) - mu*mu;
            s_mu = mu;
            s_inv = rsqrtf(var + 1e-5f);
        }
    }
    __syncthreads();
    float mu = s_mu, inv = s_inv;
    for (int c = tid; c < DM; c += 256)
        out[(size_t)row*DM + c] = (ybuf[c] - mu)*inv*gamma[c] + beta[c];
}

// ============================================================
extern "C" void kernel_launch(void* const* d_in, const int* in_sizes, int n_in,
                              void* d_out, int out_size)
{
    const float*         x     = (const float*)d_in[0];
    const unsigned char* am    = (const unsigned char*)d_in[1];
    const float*         Wq    = (const float*)d_in[2];
    const float*         bq    = (const float*)d_in[3];
    const float*         Wk    = (const float*)d_in[4];
    const float*         bk    = (const float*)d_in[5];
    const float*         Wv    = (const float*)d_in[6];
    const float*         bv    = (const float*)d_in[7];
    const float*         gamma = (const float*)d_in[8];
    const float*         beta  = (const float*)d_in[9];
    float*               out   = (float*)d_out;
    (void)in_sizes; (void)n_in; (void)out_size;

    const int SM_QKV = 2*128*72*2*2;                    // 73728
    const int SM_SC  = 2*128*72*2*2 + 2*128*4;          // 74752
    const int SM_AV  = (2*128*64 + 2*64*200 + 128*72)*2;// 102400

    cudaFuncSetAttribute(k_qkv,    cudaFuncAttributeMaxDynamicSharedMemorySize, SM_QKV);
    cudaFuncSetAttribute(k_scores, cudaFuncAttributeMaxDynamicSharedMemorySize, SM_SC);
    cudaFuncSetAttribute(k_av,     cudaFuncAttributeMaxDynamicSharedMemorySize, SM_AV);

    k_cvt_x<<<BATCH*SEQ*DM/1024, 256>>>(x);
    k_cvt_w<<<dim3(DM*DM/1024, 3), 256>>>(Wq, Wk, Wv);

    k_qkv<<<dim3(3*DM/128, BATCH*SEQ/128), 256, SM_QKV>>>(bq, bk, bv);

    const int NT = (SEQ/128)*(SEQ/128 + 1)/2;   // 136 lower-tri tiles
    k_scores<<<dim3(NT, BHT), 256, SM_SC>>>(am);

    k_red<<<BHT*SEQ/256, 256>>>();

    k_av<<<dim3(40, BHT), 256, SM_AV>>>();

    k_ln<<<BATCH*SEQ, 256>>>(x, gamma, beta, out);
}

// round 8
// speedup vs baseline: 8.4844x; 1.0277x over previous
#include <cuda_runtime.h>
#include <cuda_fp16.h>
#include <math.h>
#include <stdint.h>

#define SEQ    2048
#define DM     768
#define NH     4
#define HD     192
#define BATCH  4
#define BHT    16
#define NEGH   (-60000.0f)
// 0.05 * log2(e)
#define SC2    (0.07213475204444817f)

// ---- device scratch ----
__device__ __align__(16) __half g_Xh [BATCH*SEQ*DM];
__device__ __align__(16) __half g_Wh [3*DM*DM];
__device__ __align__(16) __half g_Qh [BHT*SEQ*HD];
__device__ __align__(16) __half g_Kh [BHT*SEQ*HD];
__device__ __align__(16) __half g_Vh [BHT*SEQ*HD];
__device__ __align__(16) __half g_Sch[(size_t)BHT*SEQ*SEQ];   // s * 0.05 * log2e
__device__ float  g_pl [BHT*16*SEQ];    // partial sum of 2^s'
__device__ float  g_lse[BHT*SEQ];       // log2(sum 2^s')
__device__ __align__(16) __half g_X1p[4*BHT*SEQ*HD];

// ---------------- helpers ----------------
__device__ __forceinline__ unsigned sptr(const void* p){
    return (unsigned)__cvta_generic_to_shared(p);
}
__device__ __forceinline__ void cpa16(unsigned dst, const void* src){
    asm volatile("cp.async.cg.shared.global [%0], [%1], 16;\n" :: "r"(dst), "l"(src));
}
__device__ __forceinline__ void cpa_commit(){ asm volatile("cp.async.commit_group;\n"); }
__device__ __forceinline__ void cpa_wait_all(){ asm volatile("cp.async.wait_group 0;\n"); }

__device__ __forceinline__ void ldsm4(unsigned r[4], unsigned a){
    asm volatile("ldmatrix.sync.aligned.m8n8.x4.shared.b16 {%0,%1,%2,%3},[%4];\n"
        : "=r"(r[0]),"=r"(r[1]),"=r"(r[2]),"=r"(r[3]) : "r"(a));
}
__device__ __forceinline__ void ldsm4t(unsigned r[4], unsigned a){
    asm volatile("ldmatrix.sync.aligned.m8n8.x4.trans.shared.b16 {%0,%1,%2,%3},[%4];\n"
        : "=r"(r[0]),"=r"(r[1]),"=r"(r[2]),"=r"(r[3]) : "r"(a));
}
__device__ __forceinline__ void mma16816(float* c, const unsigned* a, unsigned b0, unsigned b1){
    asm volatile("mma.sync.aligned.m16n8k16.row.col.f32.f16.f16.f32 "
        "{%0,%1,%2,%3},{%4,%5,%6,%7},{%8,%9},{%0,%1,%2,%3};\n"
        : "+f"(c[0]),"+f"(c[1]),"+f"(c[2]),"+f"(c[3])
        : "r"(a[0]),"r"(a[1]),"r"(a[2]),"r"(a[3]),"r"(b0),"r"(b1));
}

// ---------------- fused conversion: x and Wq|Wk|Wv in one launch ----------------
#define NX4 (BATCH*SEQ*DM/4)        // 1,572,864 float4 units for x
#define NW4 (DM*DM/4)               // 147,456 per weight
__global__ __launch_bounds__(256) void k_cvt(
    const float* __restrict__ x,
    const float* __restrict__ Wq, const float* __restrict__ Wk, const float* __restrict__ Wv)
{
    int i = blockIdx.x*256 + threadIdx.x;
    const float* src;
    __half* dst;
    int j;
    if (i < NX4){ src = x; dst = g_Xh; j = i; }
    else {
        int t = i - NX4;
        int w = t / NW4;  j = t - w*NW4;
        src = (w==0)?Wq:((w==1)?Wk:Wv);
        dst = g_Wh + (size_t)w*DM*DM;
    }
    float4 v = *(const float4*)(src + (size_t)j*4);
    *(__half2*)&dst[(size_t)j*4]   = __floats2half2_rn(v.x,v.y);
    *(__half2*)&dst[(size_t)j*4+2] = __floats2half2_rn(v.z,v.w);
}

// ============================================================
// K1: QKV projection GEMM-NT, cp.async double-buffered (HMMA)
// ============================================================
__global__ __launch_bounds__(256,2) void k_qkv(
    const float* __restrict__ bq, const float* __restrict__ bk, const float* __restrict__ bv)
{
    extern __shared__ __align__(16) char smraw[];
    __half* As = (__half*)smraw;            // [2][128][72]
    __half* Bs = As + 2*128*72;             // [2][128][72]

    const int n0 = blockIdx.x*128, m0 = blockIdx.y*128;
    const int tid = threadIdx.x, lane = tid&31, wid = tid>>5;
    const int wm = wid>>2, wn = wid&3;
    const int lrow = lane&15, lcol = (lane>>4)*8;

    float acc[4][4][4] = {};
    const int ldr = tid>>3, ldc = (tid&7)*8;

    #pragma unroll
    for (int i=0;i<4;i++){
        int row = ldr + 32*i;
        cpa16(sptr(&As[(size_t)row*72 + ldc]), &g_Xh[(size_t)(m0+row)*DM + ldc]);
        cpa16(sptr(&Bs[(size_t)row*72 + ldc]), &g_Wh[(size_t)(n0+row)*DM + ldc]);
    }
    cpa_commit();

    const int NIT = DM/64;
    for (int it=0; it<NIT; it++){
        int cur = it & 1;
        cpa_wait_all();
        __syncthreads();
        if (it+1 < NIT){
            int nb = (it+1)&1, kb = (it+1)*64;
            #pragma unroll
            for (int i=0;i<4;i++){
                int row = ldr + 32*i;
                cpa16(sptr(&As[(size_t)(nb*128+row)*72 + ldc]), &g_Xh[(size_t)(m0+row)*DM + kb + ldc]);
                cpa16(sptr(&Bs[(size_t)(nb*128+row)*72 + ldc]), &g_Wh[(size_t)(n0+row)*DM + kb + ldc]);
            }
            cpa_commit();
        }
        const __half* Ab = As + (size_t)cur*128*72;
        const __half* Bb = Bs + (size_t)cur*128*72;
        #pragma unroll
        for (int kk=0;kk<4;kk++){
            unsigned a[4][4], b[2][4];
            #pragma unroll
            for (int mi=0;mi<4;mi++)
                ldsm4(a[mi], sptr(&Ab[(size_t)(wm*64+mi*16+lrow)*72 + kk*16+lcol]));
            #pragma unroll
            for (int np=0;np<2;np++)
                ldsm4(b[np], sptr(&Bb[(size_t)(wn*32+np*16+lrow)*72 + kk*16+lcol]));
            #pragma unroll
            for (int mi=0;mi<4;mi++)
                #pragma unroll
                for (int ni=0;ni<4;ni++)
                    mma16816(acc[mi][ni], a[mi], b[ni>>1][ni&1], b[ni>>1][(ni&1)+2]);
        }
        __syncthreads();
    }

    const int w = n0/DM;
    const float* bias = (w==0)?bq:((w==1)?bk:bv);
    __half* Out = (w==0)?g_Qh:((w==1)?g_Kh:g_Vh);

    #pragma unroll
    for (int mi=0;mi<4;mi++){
        int r0 = m0 + wm*64 + mi*16 + (lane>>2);
        #pragma unroll
        for (int ni=0;ni<4;ni++){
            int n = n0 + wn*32 + ni*8 + (lane&3)*2;
            int c = n - w*DM;
            int h = c/HD, d = c - h*HD;
            float b0f = bias[c], b1f = bias[c+1];
            #pragma unroll
            for (int p=0;p<2;p++){
                int m = r0 + p*8;
                int b_ = m>>11, s_ = m&(SEQ-1);
                __half2 hv = __floats2half2_rn(acc[mi][ni][2*p]+b0f, acc[mi][ni][2*p+1]+b1f);
                *(__half2*)&Out[((size_t)((b_*NH+h)*SEQ+s_))*HD + d] = hv;
            }
        }
    }
}

// ============================================================
// K2: scores (base-2 domain) + fused per-tile column sum of 2^s'
// ============================================================
__global__ __launch_bounds__(256,2) void k_scores(const unsigned char* __restrict__ am)
{
    extern __shared__ __align__(16) char smraw[];
    __half* As = (__half*)smraw;
    __half* Bs = As + 2*128*72;
    float*  pl = (float*)(Bs + 2*128*72);

    const int bh = blockIdx.y, b_ = bh>>2;
    int t = blockIdx.x;
    int qt = (int)((sqrtf(8.f*(float)t+1.f)-1.f)*0.5f);
    while ((qt+1)*(qt+2)/2 <= t) ++qt;
    while (qt*(qt+1)/2 > t)      --qt;
    int kt = t - qt*(qt+1)/2;
    const int q0 = qt*128, k0 = kt*128;
    const bool diag = (kt == qt);

    const __half* Qp = g_Qh + (size_t)bh*SEQ*HD;
    const __half* Kp = g_Kh + (size_t)bh*SEQ*HD;
    __half* Sp = g_Sch + (size_t)bh*SEQ*SEQ;

    const int tid = threadIdx.x, lane = tid&31, wid = tid>>5;
    const int wm = wid>>2, wn = wid&3;
    const int lrow = lane&15, lcol = (lane>>4)*8;
    const int ldr = tid>>3, ldc = (tid&7)*8;

    float acc[4][4][4] = {};

    #pragma unroll
    for (int i=0;i<4;i++){
        int row = ldr + 32*i;
        cpa16(sptr(&As[(size_t)row*72 + ldc]), &Qp[(size_t)(q0+row)*HD + ldc]);
        cpa16(sptr(&Bs[(size_t)row*72 + ldc]), &Kp[(size_t)(k0+row)*HD + ldc]);
    }
    cpa_commit();

    const int NIT = HD/64;
    for (int it=0; it<NIT; it++){
        int cur = it & 1;
        cpa_wait_all();
        __syncthreads();
        if (it+1 < NIT){
            int nb = (it+1)&1, kb = (it+1)*64;
            #pragma unroll
            for (int i=0;i<4;i++){
                int row = ldr + 32*i;
                cpa16(sptr(&As[(size_t)(nb*128+row)*72 + ldc]), &Qp[(size_t)(q0+row)*HD + kb + ldc]);
                cpa16(sptr(&Bs[(size_t)(nb*128+row)*72 + ldc]), &Kp[(size_t)(k0+row)*HD + kb + ldc]);
            }
            cpa_commit();
        }
        const __half* Ab = As + (size_t)cur*128*72;
        const __half* Bb = Bs + (size_t)cur*128*72;
        #pragma unroll
        for (int kk=0;kk<4;kk++){
            unsigned a[4][4], b[2][4];
            #pragma unroll
            for (int mi=0;mi<4;mi++)
                ldsm4(a[mi], sptr(&Ab[(size_t)(wm*64+mi*16+lrow)*72 + kk*16+lcol]));
            #pragma unroll
            for (int np=0;np<2;np++)
                ldsm4(b[np], sptr(&Bb[(size_t)(wn*32+np*16+lrow)*72 + kk*16+lcol]));
            #pragma unroll
            for (int mi=0;mi<4;mi++)
                #pragma unroll
                for (int ni=0;ni<4;ni++)
                    mma16816(acc[mi][ni], a[mi], b[ni>>1][ni&1], b[ni>>1][(ni&1)+2]);
        }
        __syncthreads();
    }

    float coll[4][2];
    #pragma unroll
    for (int ni=0;ni<4;ni++){ coll[ni][0]=coll[ni][1]=0.f; }

    #pragma unroll
    for (int mi=0;mi<4;mi++){
        int r0 = q0 + wm*64 + mi*16 + (lane>>2);
        #pragma unroll
        for (int p=0;p<2;p++){
            int q = r0 + p*8;
            bool pad = am[b_*SEQ + q] != 0;
            #pragma unroll
            for (int ni=0;ni<4;ni++){
                int k = k0 + wn*32 + ni*8 + (lane&3)*2;
                float v0, v1;
                if (diag){
                    v0 = (k   > q || pad) ? NEGH : acc[mi][ni][2*p]  *SC2;
                    v1 = (k+1 > q || pad) ? NEGH : acc[mi][ni][2*p+1]*SC2;
                } else {
                    v0 = pad ? NEGH : acc[mi][ni][2*p]  *SC2;
                    v1 = pad ? NEGH : acc[mi][ni][2*p+1]*SC2;
                }
                __half2 h2 = __floats2half2_rn(v0,v1);
                *(__half2*)&Sp[(size_t)q*SEQ + k] = h2;
                float2 f = __half22float2(h2);
                coll[ni][0] += exp2f(f.x);      // 2^(-60000) underflows to 0
                coll[ni][1] += exp2f(f.y);
            }
        }
    }
    #pragma unroll
    for (int off=4; off<32; off<<=1){
        #pragma unroll
        for (int ni=0;ni<4;ni++){
            coll[ni][0] += __shfl_xor_sync(0xffffffffu, coll[ni][0], off);
            coll[ni][1] += __shfl_xor_sync(0xffffffffu, coll[ni][1], off);
        }
    }
    if (lane < 4){
        #pragma unroll
        for (int ni=0;ni<4;ni++){
            int col = wn*32 + ni*8 + lane*2;
            pl[wm*128 + col]     = coll[ni][0];
            pl[wm*128 + col + 1] = coll[ni][1];
        }
    }
    __syncthreads();
    if (tid < 128){
        size_t o = ((size_t)(bh*16 + qt))*SEQ + k0 + tid;
        g_pl[o] = pl[tid] + pl[128+tid];
    }
}

// ============================================================
// K3: reduce column partial sums over qt -> lse (log2 domain)
// ============================================================
__global__ __launch_bounds__(256) void k_red()
{
    int idx = blockIdx.x*256 + threadIdx.x;
    int bh = idx >> 11;
    int k  = idx & (SEQ-1);
    int kt = k >> 7;
    float l = 0.f;
    for (int qt = kt; qt < 16; qt++)
        l += g_pl[((size_t)(bh*16 + qt))*SEQ + k];
    g_lse[idx] = __log2f(l);
}

// ============================================================
// K4: X1 partial = P@V split-K, P = 2^(s' - lse')
// ============================================================
__global__ __launch_bounds__(256,2) void k_av()
{
    extern __shared__ __align__(16) char smraw[];
    __half* Ss = (__half*)smraw;
    __half* Vs = Ss + 2*128*64;
    __half* Ps = Vs + 2*64*200;

    int idx = 39 - (int)blockIdx.x;
    int g, base;
    if      (idx < 4)  { g=0; base=0;  }
    else if (idx < 12) { g=1; base=4;  }
    else if (idx < 24) { g=2; base=12; }
    else               { g=3; base=24; }
    int off = idx - base;
    const int qt = 4*g + off/(g+1);
    const int ks = off % (g+1);

    const int bh = blockIdx.y;
    const int q0 = qt*128;
    const int kstart = ks*512;
    const int kend   = min(kstart+512, (qt+1)*128);

    const __half* Vp = g_Vh + (size_t)bh*SEQ*HD;
    const __half* Sp = g_Sch + (size_t)bh*SEQ*SEQ;
    const float* lse = g_lse + bh*SEQ;

    const int tid = threadIdx.x, lane = tid&31, wid = tid>>5;
    const int wm = wid>>2, wn = wid&3;
    const int lrow = lane&15, lcol = (lane>>4)*8;

    float acc[4][6][4] = {};
    const int srow = tid>>3, svc = (tid&7)*8;

    {
        #pragma unroll
        for (int i=0;i<4;i++){
            int row = srow + 32*i;
            cpa16(sptr(&Ss[(size_t)row*64 + svc]), &Sp[(size_t)(q0+row)*SEQ + kstart + svc]);
        }
        #pragma unroll
        for (int i=0;i<6;i++){
            int ii = tid + 256*i;
            int row = ii/24, vc = (ii%24)*8;
            cpa16(sptr(&Vs[(size_t)row*200 + vc]), &Vp[(size_t)(kstart+row)*HD + vc]);
        }
        cpa_commit();
    }

    const int NIT = (kend - kstart) >> 6;
    for (int it=0; it<NIT; it++){
        int cur = it & 1;
        cpa_wait_all();
        __syncthreads();
        if (it+1 < NIT){
            int nb = (it+1)&1, kb = kstart + (it+1)*64;
            #pragma unroll
            for (int i=0;i<4;i++){
                int row = srow + 32*i;
                cpa16(sptr(&Ss[(size_t)(nb*128+row)*64 + svc]), &Sp[(size_t)(q0+row)*SEQ + kb + svc]);
            }
            #pragma unroll
            for (int i=0;i<6;i++){
                int ii = tid + 256*i;
                int row = ii/24, vc = (ii%24)*8;
                cpa16(sptr(&Vs[(size_t)(nb*64+row)*200 + vc]), &Vp[(size_t)(kb+row)*HD + vc]);
            }
            cpa_commit();
        }
        const __half* Sb = Ss + (size_t)cur*128*64;
        int kbase = kstart + it*64;
        #pragma unroll
        for (int i=0;i<4;i++){
            int row = srow + 32*i;
            uint4 raw = *(const uint4*)&Sb[(size_t)row*64 + svc];
            __half2* hp = (__half2*)&raw;
            __half2 o[4];
            #pragma unroll
            for (int j=0;j<4;j++){
                float2 f = __half22float2(hp[j]);
                int k2 = kbase + svc + j*2;
                float e0 = exp2f(f.x - __ldg(&lse[k2]));
                float e1 = exp2f(f.y - __ldg(&lse[k2+1]));
                o[j] = __floats2half2_rn(e0,e1);
            }
            *(uint4*)&Ps[(size_t)row*72 + svc] = *(uint4*)o;
        }
        __syncthreads();
        const __half* Vb = Vs + (size_t)cur*64*200;
        #pragma unroll
        for (int kk=0;kk<4;kk++){
            unsigned a[4][4], b[3][4];
            #pragma unroll
            for (int mi=0;mi<4;mi++)
                ldsm4(a[mi], sptr(&Ps[(size_t)(wm*64+mi*16+lrow)*72 + kk*16+lcol]));
            #pragma unroll
            for (int np=0;np<3;np++)
                ldsm4t(b[np], sptr(&Vb[(size_t)(kk*16+lrow)*200 + wn*48+np*16+lcol]));
            #pragma unroll
            for (int mi=0;mi<4;mi++)
                #pragma unroll
                for (int ni=0;ni<6;ni++)
                    mma16816(acc[mi][ni], a[mi], b[ni>>1][(ni&1)*2], b[ni>>1][(ni&1)*2+1]);
        }
    }

    __half* Xp = g_X1p + (size_t)ks*BHT*SEQ*HD;
    #pragma unroll
    for (int mi=0;mi<4;mi++){
        int r0 = q0 + wm*64 + mi*16 + (lane>>2);
        #pragma unroll
        for (int ni=0;ni<6;ni++){
            int d = wn*48 + ni*8 + (lane&3)*2;
            #pragma unroll
            for (int p=0;p<2;p++){
                int q = r0 + p*8;
                *(__half2*)&Xp[((size_t)(bh*SEQ+q))*HD + d] =
                    __floats2half2_rn(acc[mi][ni][2*p], acc[mi][ni][2*p+1]);
            }
        }
    }
}

// ============================================================
// K5: y = x + sum(X1 partials), LayerNorm — 384 thr, 2 ch/thread
// ============================================================
__global__ __launch_bounds__(384) void k_ln(
    const float* __restrict__ x,
    const float* __restrict__ gamma,
    const float* __restrict__ beta,
    float* __restrict__ out)
{
    int row = blockIdx.x;
    int b_ = row >> 11, s_ = row & (SEQ-1);
    int tid = threadIdx.x;
    int ns = (s_ >> 9) + 1;
    int c = tid*2;

    __shared__ float rs[12], rq[12];
    __shared__ float s_mu, s_inv;

    int h_ = c/HD, d_ = c - h_*HD;
    size_t o = ((size_t)((b_*NH+h_)*SEQ+s_))*HD + d_;
    float2 xv = *(const float2*)&x[(size_t)row*DM + c];
    float v0 = xv.x, v1 = xv.y;
    for (int s = 0; s < ns; s++){
        __half2 hp = *(const __half2*)&g_X1p[(size_t)s*BHT*SEQ*HD + o];
        float2 f = __half22float2(hp);
        v0 += f.x; v1 += f.y;
    }
    float sum = v0 + v1;
    float sq  = v0*v0 + v1*v1;

    #pragma unroll
    for (int of = 16; of; of >>= 1){
        sum += __shfl_down_sync(0xffffffffu, sum, of);
        sq  += __shfl_down_sync(0xffffffffu, sq , of);
    }
    int wid = tid >> 5, lane = tid & 31;
    if (lane == 0){ rs[wid] = sum; rq[wid] = sq; }
    __syncthreads();
    if (tid < 32){
        sum = (tid < 12) ? rs[tid] : 0.0f;
        sq  = (tid < 12) ? rq[tid] : 0.0f;
        #pragma unroll
        for (int of = 16; of; of >>= 1){
            sum += __shfl_down_sync(0xffffffffu, sum, of);
            sq  += __shfl_down_sync(0xffffffffu, sq , of);
        }
        if (tid == 0){
            float mu  = sum * (1.0f/DM);
            float var = sq  * (1.0f/DM) - mu*mu;
            s_mu = mu;
            s_inv = rsqrtf(var + 1e-5f);
        }
    }
    __syncthreads();
    float mu = s_mu, inv = s_inv;
    float2 gv = *(const float2*)&gamma[c];
    float2 bv = *(const float2*)&beta[c];
    float2 ov;
    ov.x = (v0 - mu)*inv*gv.x + bv.x;
    ov.y = (v1 - mu)*inv*gv.y + bv.y;
    *(float2*)&out[(size_t)row*DM + c] = ov;
}

// ============================================================
extern "C" void kernel_launch(void* const* d_in, const int* in_sizes, int n_in,
                              void* d_out, int out_size)
{
    const float*         x     = (const float*)d_in[0];
    const unsigned char* am    = (const unsigned char*)d_in[1];
    const float*         Wq    = (const float*)d_in[2];
    const float*         bq    = (const float*)d_in[3];
    const float*         Wk    = (const float*)d_in[4];
    const float*         bk    = (const float*)d_in[5];
    const float*         Wv    = (const float*)d_in[6];
    const float*         bv    = (const float*)d_in[7];
    const float*         gamma = (const float*)d_in[8];
    const float*         beta  = (const float*)d_in[9];
    float*               out   = (float*)d_out;
    (void)in_sizes; (void)n_in; (void)out_size;

    const int SM_QKV = 2*128*72*2*2;                    // 73728
    const int SM_SC  = 2*128*72*2*2 + 2*128*4;          // 74752
    const int SM_AV  = (2*128*64 + 2*64*200 + 128*72)*2;// 102400

    cudaFuncSetAttribute(k_qkv,    cudaFuncAttributeMaxDynamicSharedMemorySize, SM_QKV);
    cudaFuncSetAttribute(k_scores, cudaFuncAttributeMaxDynamicSharedMemorySize, SM_SC);
    cudaFuncSetAttribute(k_av,     cudaFuncAttributeMaxDynamicSharedMemorySize, SM_AV);

    k_cvt<<<(NX4 + 3*NW4)/256, 256>>>(x, Wq, Wk, Wv);

    k_qkv<<<dim3(3*DM/128, BATCH*SEQ/128), 256, SM_QKV>>>(bq, bk, bv);

    const int NT = (SEQ/128)*(SEQ/128 + 1)/2;   // 136 lower-tri tiles
    k_scores<<<dim3(NT, BHT), 256, SM_SC>>>(am);

    k_red<<<BHT*SEQ/256, 256>>>();

    k_av<<<dim3(40, BHT), 256, SM_AV>>>();

    k_ln<<<BATCH*SEQ, 384>>>(x, gamma, beta, out);
}